// round 4
// baseline (speedup 1.0000x reference)
#include <cuda_runtime.h>
#include <cuda_bf16.h>
#include <cstdint>

#define B_  2
#define L_  2048
#define D_  1024
#define H_  16
#define HD_ 64
#define MROWS 4096
#define KSPLIT 3072
#define HSZ (B_ * H_ * L_ * HD_)

// ---------------- scratch (static device globals; no allocation allowed) ----
__device__ __nv_bfloat16 g_A[3][MROWS * KSPLIT];     // split activations (q,k,v) ; [0] reused for attn-out
__device__ __nv_bfloat16 g_Wt[4][D_ * KSPLIT];       // split transposed weights
__device__ __nv_bfloat16 g_QKVh[3][HSZ];             // projected q/k/v hi  [B,H,L,HD]
__device__ __nv_bfloat16 g_QKVl[3][HSZ];             // projected q/k/v lo

// ============================================================================
// helpers
// ============================================================================
__device__ __forceinline__ uint32_t smem_u32(const void* p) {
    uint32_t a;
    asm("{ .reg .u64 t; cvta.to.shared.u64 t, %1; cvt.u32.u64 %0, t; }" : "=r"(a) : "l"(p));
    return a;
}
__device__ __forceinline__ void cp16(uint32_t dst, const void* src) {
    asm volatile("cp.async.cg.shared.global [%0], [%1], 16;" :: "r"(dst), "l"(src));
}
#define CPCOMMIT() asm volatile("cp.async.commit_group;" ::: "memory")
#define CPWAIT(n)  asm volatile("cp.async.wait_group %0;" :: "n"(n) : "memory")

__device__ __forceinline__ void ldsm4(uint32_t r[4], uint32_t addr) {
    asm volatile("ldmatrix.sync.aligned.m8n8.x4.shared.b16 {%0,%1,%2,%3}, [%4];"
        : "=r"(r[0]), "=r"(r[1]), "=r"(r[2]), "=r"(r[3]) : "r"(addr));
}
__device__ __forceinline__ void ldsm4t(uint32_t r[4], uint32_t addr) {
    asm volatile("ldmatrix.sync.aligned.m8n8.x4.trans.shared.b16 {%0,%1,%2,%3}, [%4];"
        : "=r"(r[0]), "=r"(r[1]), "=r"(r[2]), "=r"(r[3]) : "r"(addr));
}
__device__ __forceinline__ void mma16816(float c[4], const uint32_t a[4],
                                         uint32_t b0, uint32_t b1) {
    asm volatile("mma.sync.aligned.m16n8k16.row.col.f32.bf16.bf16.f32 "
        "{%0,%1,%2,%3}, {%4,%5,%6,%7}, {%8,%9}, {%0,%1,%2,%3};"
        : "+f"(c[0]), "+f"(c[1]), "+f"(c[2]), "+f"(c[3])
        : "r"(a[0]), "r"(a[1]), "r"(a[2]), "r"(a[3]), "r"(b0), "r"(b1));
}
__device__ __forceinline__ uint32_t pack_bf2(float hiVal, float loVal) {
    uint32_t r;
    asm("cvt.rn.bf16x2.f32 %0, %1, %2;" : "=r"(r) : "f"(hiVal), "f"(loVal));
    return r;
}

// ============================================================================
// batched split conversions
// ============================================================================
__global__ void split_rows3(const float* __restrict__ X0, const float* __restrict__ X1,
                            const float* __restrict__ X2, __nv_bfloat16* __restrict__ Abase)
{
    const int z = blockIdx.y;
    const float* X = (z == 0) ? X0 : (z == 1) ? X1 : X2;
    __nv_bfloat16* A = Abase + (size_t)z * MROWS * KSPLIT;
    const int idx = blockIdx.x * 256 + threadIdx.x;
    const int r = idx >> 8;
    const int c = (idx & 255) << 2;
    float4 v = *(const float4*)(X + (size_t)r * D_ + c);
    float vf[4] = {v.x, v.y, v.z, v.w};
    ushort4 hv, lv;
    unsigned short* hp = &hv.x;
    unsigned short* lp = &lv.x;
#pragma unroll
    for (int j = 0; j < 4; j++) {
        __nv_bfloat16 hi = __float2bfloat16(vf[j]);
        __nv_bfloat16 lo = __float2bfloat16(vf[j] - __bfloat162float(hi));
        hp[j] = __bfloat16_as_ushort(hi);
        lp[j] = __bfloat16_as_ushort(lo);
    }
    __nv_bfloat16* row = A + (size_t)r * KSPLIT;
    *(ushort4*)(row + c)        = hv;
    *(ushort4*)(row + D_ + c)   = lv;
    *(ushort4*)(row + 2*D_ + c) = hv;
}

__global__ void split_weightT4(const float* __restrict__ W0, const float* __restrict__ W1,
                               const float* __restrict__ W2, const float* __restrict__ W3,
                               __nv_bfloat16* __restrict__ WtBase)
{
    __shared__ float t[32][33];
    const int z = blockIdx.z;
    const float* W = (z == 0) ? W0 : (z == 1) ? W1 : (z == 2) ? W2 : W3;
    __nv_bfloat16* Wt = WtBase + (size_t)z * D_ * KSPLIT;
    const int k0 = blockIdx.x * 32, n0 = blockIdx.y * 32;
    const int tx = threadIdx.x, ty = threadIdx.y;
    for (int i = ty; i < 32; i += 8)
        t[i][tx] = W[(size_t)(k0 + i) * D_ + n0 + tx];
    __syncthreads();
    for (int i = ty; i < 32; i += 8) {
        const float x = t[tx][i];
        __nv_bfloat16 hi = __float2bfloat16(x);
        __nv_bfloat16 lo = __float2bfloat16(x - __bfloat162float(hi));
        __nv_bfloat16* row = Wt + (size_t)(n0 + i) * KSPLIT + k0 + tx;
        row[0]    = hi;
        row[D_]   = hi;
        row[2*D_] = lo;
    }
}

// ============================================================================
// mma.sync GEMM core: CTA 256x128, 512 threads, warp 64x32, 3-stage cp.async
// ============================================================================
#define G_STAGE 49152
#define G_SMEM  (3 * G_STAGE)

template <int MODE>   // 0: fp32 [M,D] out, 1: bf16 hi/lo head-layout out
__device__ __forceinline__
void gemm_core(const __nv_bfloat16* __restrict__ A, const __nv_bfloat16* __restrict__ Bt,
               const float* __restrict__ bias, float* __restrict__ OutF,
               __nv_bfloat16* __restrict__ OutH, __nv_bfloat16* __restrict__ OutL,
               float scale)
{
    extern __shared__ __align__(128) char smem[];
    const uint32_t sb = smem_u32(smem);
    const int tid = threadIdx.x, lane = tid & 31, warp = tid >> 5;
    const int wm = warp >> 2, wn = warp & 3;
    const int rowBase = blockIdx.y * 256;
    const int colBase = blockIdx.x * 128;

    float c[4][4][4];
#pragma unroll
    for (int i = 0; i < 4; i++)
#pragma unroll
        for (int j = 0; j < 4; j++)
#pragma unroll
            for (int k = 0; k < 4; k++) c[i][j][k] = 0.f;

    const int lr = tid >> 3, lg = tid & 7;

    auto issue = [&](int chunk, int s) {
        const uint32_t SA = sb + s * G_STAGE, SB = SA + 32768;
        const int c0 = chunk * 64;
#pragma unroll
        for (int j = 0; j < 4; j++) {
            const int r = 64 * j + lr;
            cp16(SA + r * 128 + ((lg ^ (r & 7)) << 4),
                 A + (size_t)(rowBase + r) * KSPLIT + c0 + lg * 8);
        }
#pragma unroll
        for (int j = 0; j < 2; j++) {
            const int r = 64 * j + lr;
            cp16(SB + r * 128 + ((lg ^ (r & 7)) << 4),
                 Bt + (size_t)(colBase + r) * KSPLIT + c0 + lg * 8);
        }
    };

    issue(0, 0); CPCOMMIT();
    issue(1, 1); CPCOMMIT();

    for (int ch = 0; ch < 48; ch++) {
        __syncthreads();
        if (ch + 2 < 48) issue(ch + 2, (ch + 2) % 3);
        CPCOMMIT();
        CPWAIT(2);
        __syncthreads();

        const uint32_t SA = sb + (ch % 3) * G_STAGE, SB = SA + 32768;
#pragma unroll
        for (int kk = 0; kk < 4; kk++) {
            const int g = 2 * kk + (lane >> 4);
            uint32_t af[4][4];
#pragma unroll
            for (int mt = 0; mt < 4; mt++) {
                const int r = 64 * wm + 16 * mt + (lane & 15);
                ldsm4(af[mt], SA + r * 128 + ((g ^ (r & 7)) << 4));
            }
#pragma unroll
            for (int ntp = 0; ntp < 2; ntp++) {
                uint32_t bf[4];
                const int r = 32 * wn + 16 * ntp + (lane & 15);
                ldsm4(bf, SB + r * 128 + ((g ^ (r & 7)) << 4));
#pragma unroll
                for (int mt = 0; mt < 4; mt++) {
                    mma16816(c[mt][2*ntp],   af[mt], bf[0], bf[2]);
                    mma16816(c[mt][2*ntp+1], af[mt], bf[1], bf[3]);
                }
            }
        }
    }

#pragma unroll
    for (int mt = 0; mt < 4; mt++)
#pragma unroll
        for (int nt = 0; nt < 4; nt++) {
            const int n0 = colBase + 32 * wn + 8 * nt + (lane & 3) * 2;
            const float b0v = bias[n0], b1v = bias[n0 + 1];
#pragma unroll
            for (int h = 0; h < 2; h++) {
                const int m = rowBase + 64 * wm + 16 * mt + 8 * h + (lane >> 2);
                float v0 = c[mt][nt][2*h]   + b0v;
                float v1 = c[mt][nt][2*h+1] + b1v;
                if (MODE == 1) {
                    v0 *= scale; v1 *= scale;
                    const uint32_t hi = pack_bf2(v1, v0);
                    const float f0 = __uint_as_float(hi << 16);
                    const float f1 = __uint_as_float(hi & 0xffff0000u);
                    const uint32_t lo = pack_bf2(v1 - f1, v0 - f0);
                    const int bb = m >> 11, l = m & (L_ - 1);
                    const int hh = n0 >> 6, d = n0 & (HD_ - 1);
                    const size_t idx = ((size_t)(bb * H_ + hh) * L_ + l) * HD_ + d;
                    *(uint32_t*)((char*)OutH + idx * 2) = hi;
                    *(uint32_t*)((char*)OutL + idx * 2) = lo;
                } else {
                    float2 v = {v0, v1};
                    *(float2*)(OutF + (size_t)m * D_ + n0) = v;
                }
            }
        }
}

__global__ __launch_bounds__(512, 1)
void gemm_proj(const __nv_bfloat16* __restrict__ Abase, const __nv_bfloat16* __restrict__ WtBase,
               const float* __restrict__ bq, const float* __restrict__ bk,
               const float* __restrict__ bv,
               __nv_bfloat16* __restrict__ QKVh, __nv_bfloat16* __restrict__ QKVl)
{
    const int z = blockIdx.z;
    const __nv_bfloat16* A  = Abase  + (size_t)z * MROWS * KSPLIT;
    const __nv_bfloat16* Bt = WtBase + (size_t)z * D_ * KSPLIT;
    const float* bias = (z == 0) ? bq : (z == 1) ? bk : bv;
    gemm_core<1>(A, Bt, bias, nullptr, QKVh + (size_t)z * HSZ, QKVl + (size_t)z * HSZ,
                 (z == 0) ? 0.125f : 1.0f);
}

__global__ __launch_bounds__(512, 1)
void gemm_out(const __nv_bfloat16* __restrict__ A, const __nv_bfloat16* __restrict__ Bt,
              const float* __restrict__ bias, float* __restrict__ Out)
{
    gemm_core<0>(A, Bt, bias, Out, nullptr, nullptr, 1.0f);
}

// ============================================================================
// Flash attention v2: 256 threads / 8 warps, warp = 16 q-rows, hoisted Q frags,
// double-buffered K/V, epilogue emits hi/lo/hi split directly into A buffer.
// SMEM: Qh/Ql [128][64] = 32KB, Kh/Kl/Vh/Vl [2][64][64] = 64KB  -> 96KB
// ============================================================================
#define ATTN_SMEM 98304

__global__ __launch_bounds__(256, 1)
void attn_mma(const __nv_bfloat16* __restrict__ Qh, const __nv_bfloat16* __restrict__ Ql,
              const __nv_bfloat16* __restrict__ Kh, const __nv_bfloat16* __restrict__ Kl,
              const __nv_bfloat16* __restrict__ Vh, const __nv_bfloat16* __restrict__ Vl,
              __nv_bfloat16* __restrict__ Aout)
{
    extern __shared__ __align__(128) char smem[];
    const uint32_t sb = smem_u32(smem);
    const int tid = threadIdx.x, lane = tid & 31, w = tid >> 5;
    const int q0 = blockIdx.x * 128;
    const int bh = blockIdx.y;
    const size_t base = (size_t)bh * L_ * HD_;

    const uint32_t QHs = sb, QLs = sb + 16384;
    const uint32_t KHs = sb + 32768, KLs = sb + 49152;
    const uint32_t VHs = sb + 65536, VLs = sb + 81920;

    const int lr = tid >> 3, lg = tid & 7;

    // Q tiles: 2 arrays x 128 rows x 8 granules = 2048 cp16 / 256 thr = 8 each
#pragma unroll
    for (int j = 0; j < 8; j++) {
        const int arr = j >> 2;
        const int r = 32 * (j & 3) + lr;
        const uint32_t dst = (arr ? QLs : QHs) + r * 128 + ((lg ^ (r & 7)) << 4);
        const __nv_bfloat16* src = (arr ? Ql : Qh) + base + (size_t)(q0 + r) * HD_ + lg * 8;
        cp16(dst, src);
    }
    auto issueKV = [&](int t, int s) {
        const uint32_t bases[4] = {KHs + s * 8192, KLs + s * 8192,
                                   VHs + s * 8192, VLs + s * 8192};
        const __nv_bfloat16* srcs[4] = {Kh, Kl, Vh, Vl};
#pragma unroll
        for (int j = 0; j < 8; j++) {
            const int arr = j >> 1;
            const int r = 32 * (j & 1) + lr;
            cp16(bases[arr] + r * 128 + ((lg ^ (r & 7)) << 4),
                 srcs[arr] + base + (size_t)(t * 64 + r) * HD_ + lg * 8);
        }
    };
    issueKV(0, 0);
    CPCOMMIT();
    CPWAIT(0);
    __syncthreads();

    // hoist Q fragments (persist whole kernel)
    uint32_t qhf[4][4], qlf[4][4];
#pragma unroll
    for (int kk = 0; kk < 4; kk++) {
        const int g = 2 * kk + (lane >> 4);
        const int r = 16 * w + (lane & 15);
        const uint32_t off = r * 128 + ((g ^ (r & 7)) << 4);
        ldsm4(qhf[kk], QHs + off);
        ldsm4(qlf[kk], QLs + off);
    }

    float o[8][4];
#pragma unroll
    for (int j = 0; j < 8; j++)
#pragma unroll
        for (int k = 0; k < 4; k++) o[j][k] = 0.f;
    float mrow[2] = {-1e30f, -1e30f};
    float lrow[2] = {0.f, 0.f};

    for (int t = 0; t < 32; t++) {
        __syncthreads();
        if (t + 1 < 32) issueKV(t + 1, (t + 1) & 1);
        CPCOMMIT();
        CPWAIT(1);
        __syncthreads();
        const int s = t & 1;
        const uint32_t kh_b = KHs + s * 8192, kl_b = KLs + s * 8192;
        const uint32_t vh_b = VHs + s * 8192, vl_b = VLs + s * 8192;

        // ---- S = Q . K^T (3-term split) ----
        float sc[8][4];
#pragma unroll
        for (int j = 0; j < 8; j++)
#pragma unroll
            for (int k = 0; k < 4; k++) sc[j][k] = 0.f;

#pragma unroll
        for (int kk = 0; kk < 4; kk++) {
            const int g = 2 * kk + (lane >> 4);
#pragma unroll
            for (int ntp = 0; ntp < 4; ntp++) {
                const int r = 16 * ntp + (lane & 15);
                const uint32_t off = r * 128 + ((g ^ (r & 7)) << 4);
                uint32_t khf[4], klf[4];
                ldsm4(khf, kh_b + off);
                ldsm4(klf, kl_b + off);
                mma16816(sc[2*ntp],   qhf[kk], khf[0], khf[2]);
                mma16816(sc[2*ntp+1], qhf[kk], khf[1], khf[3]);
                mma16816(sc[2*ntp],   qlf[kk], khf[0], khf[2]);
                mma16816(sc[2*ntp+1], qlf[kk], khf[1], khf[3]);
                mma16816(sc[2*ntp],   qhf[kk], klf[0], klf[2]);
                mma16816(sc[2*ntp+1], qhf[kk], klf[1], klf[3]);
            }
        }

        // ---- online softmax ----
#pragma unroll
        for (int h = 0; h < 2; h++) {
            float tm = -1e30f;
#pragma unroll
            for (int nt = 0; nt < 8; nt++)
                tm = fmaxf(tm, fmaxf(sc[nt][2*h], sc[nt][2*h+1]));
            tm = fmaxf(tm, __shfl_xor_sync(0xffffffffu, tm, 1));
            tm = fmaxf(tm, __shfl_xor_sync(0xffffffffu, tm, 2));
            const float mn = fmaxf(mrow[h], tm);
            const float corr = __expf(mrow[h] - mn);
            mrow[h] = mn;
            float rs = 0.f;
#pragma unroll
            for (int nt = 0; nt < 8; nt++) {
                const float p0 = __expf(sc[nt][2*h]   - mn);
                const float p1 = __expf(sc[nt][2*h+1] - mn);
                sc[nt][2*h] = p0; sc[nt][2*h+1] = p1;
                rs += p0 + p1;
            }
            rs += __shfl_xor_sync(0xffffffffu, rs, 1);
            rs += __shfl_xor_sync(0xffffffffu, rs, 2);
            lrow[h] = lrow[h] * corr + rs;
#pragma unroll
            for (int nt = 0; nt < 8; nt++) {
                o[nt][2*h]   *= corr;
                o[nt][2*h+1] *= corr;
            }
        }

        // ---- O += P . V (P built in registers) ----
#pragma unroll
        for (int kk = 0; kk < 4; kk++) {
            uint32_t pah[4], pal[4];
            {
                const float* s0 = sc[2*kk];
                const float* s1 = sc[2*kk+1];
                pah[0] = pack_bf2(s0[1], s0[0]);
                pah[1] = pack_bf2(s0[3], s0[2]);
                pah[2] = pack_bf2(s1[1], s1[0]);
                pah[3] = pack_bf2(s1[3], s1[2]);
#pragma unroll
                for (int q = 0; q < 4; q++) {
                    const float* sp = (q < 2) ? s0 : s1;
                    const int e = (q & 1) * 2;
                    const uint32_t hv = pah[q];
                    const float flo = __uint_as_float(hv << 16);
                    const float fhi = __uint_as_float(hv & 0xffff0000u);
                    pal[q] = pack_bf2(sp[e + 1] - fhi, sp[e] - flo);
                }
            }
#pragma unroll
            for (int ntp = 0; ntp < 4; ntp++) {
                const int kr = 16 * kk + ((lane >> 3) & 1) * 8 + (lane & 7);
                const int g = 2 * ntp + (lane >> 4);
                const uint32_t off = kr * 128 + ((g ^ (kr & 7)) << 4);
                uint32_t vhf[4], vlf[4];
                ldsm4t(vhf, vh_b + off);
                ldsm4t(vlf, vl_b + off);
                mma16816(o[2*ntp],   pah, vhf[0], vhf[1]);
                mma16816(o[2*ntp+1], pah, vhf[2], vhf[3]);
                mma16816(o[2*ntp],   pal, vhf[0], vhf[1]);
                mma16816(o[2*ntp+1], pal, vhf[2], vhf[3]);
                mma16816(o[2*ntp],   pah, vlf[0], vlf[1]);
                mma16816(o[2*ntp+1], pah, vlf[2], vlf[3]);
            }
        }
    }

    // ---- epilogue: normalize, hi/lo split, write straight into A buffer ----
    const int b = bh >> 4, head = bh & 15;
#pragma unroll
    for (int h = 0; h < 2; h++) {
        const float inv = 1.f / lrow[h];
        const int qr = q0 + 16 * w + 8 * h + (lane >> 2);
        const int m = b * L_ + qr;
        __nv_bfloat16* rowp = Aout + (size_t)m * KSPLIT + head * HD_ + (lane & 3) * 2;
#pragma unroll
        for (int nt = 0; nt < 8; nt++) {
            const float v0 = o[nt][2*h]   * inv;
            const float v1 = o[nt][2*h+1] * inv;
            const uint32_t hi = pack_bf2(v1, v0);
            const float f0 = __uint_as_float(hi << 16);
            const float f1 = __uint_as_float(hi & 0xffff0000u);
            const uint32_t lo = pack_bf2(v1 - f1, v0 - f0);
            char* p = (char*)(rowp + 8 * nt);
            *(uint32_t*)(p)                                    = hi;   // cols [0,1024): hi
            *(uint32_t*)(p + (size_t)D_ * 2)                   = lo;   // cols [1024,2048): lo
            *(uint32_t*)(p + (size_t)2 * D_ * 2)               = hi;   // cols [2048,3072): hi
        }
    }
}

// ============================================================================
// launch
// ============================================================================
extern "C" void kernel_launch(void* const* d_in, const int* in_sizes, int n_in,
                              void* d_out, int out_size)
{
    const float* query = (const float*)d_in[0];
    const float* key_  = (const float*)d_in[1];
    const float* value = (const float*)d_in[2];
    const float* Wq = (const float*)d_in[3];
    const float* bq = (const float*)d_in[4];
    const float* Wk = (const float*)d_in[5];
    const float* bk = (const float*)d_in[6];
    const float* Wv = (const float*)d_in[7];
    const float* bv = (const float*)d_in[8];
    const float* Wo = (const float*)d_in[9];
    const float* bo = (const float*)d_in[10];
    float* out = (float*)d_out;

    __nv_bfloat16 *Ab, *Wt, *QKVh, *QKVl;
    cudaGetSymbolAddress((void**)&Ab,   g_A);
    cudaGetSymbolAddress((void**)&Wt,   g_Wt);
    cudaGetSymbolAddress((void**)&QKVh, g_QKVh);
    cudaGetSymbolAddress((void**)&QKVl, g_QKVl);

    cudaFuncSetAttribute(gemm_proj, cudaFuncAttributeMaxDynamicSharedMemorySize, G_SMEM);
    cudaFuncSetAttribute(gemm_out,  cudaFuncAttributeMaxDynamicSharedMemorySize, G_SMEM);
    cudaFuncSetAttribute(attn_mma,  cudaFuncAttributeMaxDynamicSharedMemorySize, ATTN_SMEM);

    // 1. weight splits (batched, z=4)
    dim3 wg(32, 32, 4), wb(32, 8);
    split_weightT4<<<wg, wb>>>(Wq, Wk, Wv, Wo, Wt);

    // 2. input splits (batched, z=3)
    dim3 sg(MROWS * D_ / 1024, 3);
    split_rows3<<<sg, 256>>>(query, key_, value, Ab);

    // 3. q/k/v projections (batched, z=3; 384 CTAs)
    dim3 gg(D_ / 128, MROWS / 256, 3);
    gemm_proj<<<gg, 512, G_SMEM>>>(Ab, Wt, bq, bk, bv, QKVh, QKVl);

    // 4. attention (writes split A for the output GEMM directly)
    dim3 ag(L_ / 128, B_ * H_);
    attn_mma<<<ag, 256, ATTN_SMEM>>>(QKVh, QKVl,
                                     QKVh + (size_t)1 * HSZ, QKVl + (size_t)1 * HSZ,
                                     QKVh + (size_t)2 * HSZ, QKVl + (size_t)2 * HSZ,
                                     Ab);

    // 5. output projection
    dim3 og(D_ / 128, MROWS / 256);
    gemm_out<<<og, 512, G_SMEM>>>(Ab, Wt + (size_t)3 * D_ * KSPLIT, bo, out);
}

// round 5
// speedup vs baseline: 1.5279x; 1.5279x over previous
#include <cuda_runtime.h>
#include <cuda_fp16.h>
#include <cstdint>

#define B_  2
#define L_  2048
#define D_  1024
#define H_  16
#define HD_ 64
#define MROWS 4096
#define KSPLIT 2048        // A' = [xh | xl] fp16
#define KB_ 1024           // B' = wh only (reused for both halves)
#define HSZ (B_ * H_ * L_ * HD_)

// ---------------- scratch (static device globals; no allocation allowed) ----
__device__ __half g_A[3][MROWS * KSPLIT];   // split activations; [0] reused for attn-out
__device__ __half g_Wt[4][D_ * KB_];        // transposed weight hi
__device__ __half g_QKVh[3][HSZ];           // q/k/v hi  [B,H,L,HD]
__device__ __half g_QKVl[3][HSZ];           // q/k/v lo

// ============================================================================
// helpers
// ============================================================================
__device__ __forceinline__ uint32_t smem_u32(const void* p) {
    uint32_t a;
    asm("{ .reg .u64 t; cvta.to.shared.u64 t, %1; cvt.u32.u64 %0, t; }" : "=r"(a) : "l"(p));
    return a;
}
__device__ __forceinline__ void cp16(uint32_t dst, const void* src) {
    asm volatile("cp.async.cg.shared.global [%0], [%1], 16;" :: "r"(dst), "l"(src));
}
#define CPCOMMIT() asm volatile("cp.async.commit_group;" ::: "memory")
#define CPWAIT(n)  asm volatile("cp.async.wait_group %0;" :: "n"(n) : "memory")

__device__ __forceinline__ void ldsm4(uint32_t r[4], uint32_t addr) {
    asm volatile("ldmatrix.sync.aligned.m8n8.x4.shared.b16 {%0,%1,%2,%3}, [%4];"
        : "=r"(r[0]), "=r"(r[1]), "=r"(r[2]), "=r"(r[3]) : "r"(addr));
}
__device__ __forceinline__ void ldsm4t(uint32_t r[4], uint32_t addr) {
    asm volatile("ldmatrix.sync.aligned.m8n8.x4.trans.shared.b16 {%0,%1,%2,%3}, [%4];"
        : "=r"(r[0]), "=r"(r[1]), "=r"(r[2]), "=r"(r[3]) : "r"(addr));
}
__device__ __forceinline__ void mma16816(float c[4], const uint32_t a[4],
                                         uint32_t b0, uint32_t b1) {
    asm volatile("mma.sync.aligned.m16n8k16.row.col.f32.f16.f16.f32 "
        "{%0,%1,%2,%3}, {%4,%5,%6,%7}, {%8,%9}, {%0,%1,%2,%3};"
        : "+f"(c[0]), "+f"(c[1]), "+f"(c[2]), "+f"(c[3])
        : "r"(a[0]), "r"(a[1]), "r"(a[2]), "r"(a[3]), "r"(b0), "r"(b1));
}
// pack: high half = hiVal, low half = loVal (fp16)
__device__ __forceinline__ uint32_t pack_hf2(float hiVal, float loVal) {
    uint32_t r;
    asm("cvt.rn.f16x2.f32 %0, %1, %2;" : "=r"(r) : "f"(hiVal), "f"(loVal));
    return r;
}

// ============================================================================
// batched split conversions (fp16 2-term)
// ============================================================================
__global__ void split_rows3(const float* __restrict__ X0, const float* __restrict__ X1,
                            const float* __restrict__ X2, __half* __restrict__ Abase)
{
    const int z = blockIdx.y;
    const float* X = (z == 0) ? X0 : (z == 1) ? X1 : X2;
    __half* A = Abase + (size_t)z * MROWS * KSPLIT;
    const int idx = blockIdx.x * 256 + threadIdx.x;
    const int r = idx >> 8;
    const int c = (idx & 255) << 2;
    float4 v = *(const float4*)(X + (size_t)r * D_ + c);
    float vf[4] = {v.x, v.y, v.z, v.w};
    ushort4 hv, lv;
    unsigned short* hp = &hv.x;
    unsigned short* lp = &lv.x;
#pragma unroll
    for (int j = 0; j < 4; j++) {
        __half hi = __float2half(vf[j]);
        __half lo = __float2half(vf[j] - __half2float(hi));
        hp[j] = __half_as_ushort(hi);
        lp[j] = __half_as_ushort(lo);
    }
    __half* row = A + (size_t)r * KSPLIT;
    *(ushort4*)(row + c)      = hv;
    *(ushort4*)(row + D_ + c) = lv;
}

__global__ void split_weightT4(const float* __restrict__ W0, const float* __restrict__ W1,
                               const float* __restrict__ W2, const float* __restrict__ W3,
                               __half* __restrict__ WtBase)
{
    __shared__ float t[32][33];
    const int z = blockIdx.z;
    const float* W = (z == 0) ? W0 : (z == 1) ? W1 : (z == 2) ? W2 : W3;
    __half* Wt = WtBase + (size_t)z * D_ * KB_;
    const int k0 = blockIdx.x * 32, n0 = blockIdx.y * 32;
    const int tx = threadIdx.x, ty = threadIdx.y;
    for (int i = ty; i < 32; i += 8)
        t[i][tx] = W[(size_t)(k0 + i) * D_ + n0 + tx];
    __syncthreads();
    for (int i = ty; i < 32; i += 8)
        Wt[(size_t)(n0 + i) * KB_ + k0 + tx] = __float2half(t[tx][i]);
}

// ============================================================================
// fp16 mma GEMM: C = A'[M,2048] x Wt[N,1024]^T (B reused for both K-halves)
// CTA 256x128, 512 threads, warp 64x32, 3-stage cp.async, 32 K-chunks of 64.
// ============================================================================
#define G_STAGE 49152
#define G_SMEM  (3 * G_STAGE)

template <int MODE>   // 0: fp32 [M,D] out, 1: fp16 hi/lo head-layout out
__device__ __forceinline__
void gemm_core(const __half* __restrict__ A, const __half* __restrict__ Bt,
               const float* __restrict__ bias, float* __restrict__ OutF,
               __half* __restrict__ OutH, __half* __restrict__ OutL, float scale)
{
    extern __shared__ __align__(128) char smem[];
    const uint32_t sb = smem_u32(smem);
    const int tid = threadIdx.x, lane = tid & 31, warp = tid >> 5;
    const int wm = warp >> 2, wn = warp & 3;
    const int rowBase = blockIdx.y * 256;
    const int colBase = blockIdx.x * 128;

    float c[4][4][4];
#pragma unroll
    for (int i = 0; i < 4; i++)
#pragma unroll
        for (int j = 0; j < 4; j++)
#pragma unroll
            for (int k = 0; k < 4; k++) c[i][j][k] = 0.f;

    const int lr = tid >> 3, lg = tid & 7;

    auto issue = [&](int chunk, int s) {
        const uint32_t SA = sb + s * G_STAGE, SB = SA + 32768;
        const int ca = chunk * 64;              // A col (halves)
        const int cb = (chunk & 15) * 64;       // B col (halves, hi half reused)
#pragma unroll
        for (int j = 0; j < 4; j++) {           // A: 256 rows
            const int r = 64 * j + lr;
            cp16(SA + r * 128 + ((lg ^ (r & 7)) << 4),
                 A + (size_t)(rowBase + r) * KSPLIT + ca + lg * 8);
        }
#pragma unroll
        for (int j = 0; j < 2; j++) {           // B: 128 rows
            const int r = 64 * j + lr;
            cp16(SB + r * 128 + ((lg ^ (r & 7)) << 4),
                 Bt + (size_t)(colBase + r) * KB_ + cb + lg * 8);
        }
    };

    issue(0, 0); CPCOMMIT();
    issue(1, 1); CPCOMMIT();

    for (int ch = 0; ch < 32; ch++) {
        __syncthreads();
        if (ch + 2 < 32) issue(ch + 2, (ch + 2) % 3);
        CPCOMMIT();
        CPWAIT(2);
        __syncthreads();

        const uint32_t SA = sb + (ch % 3) * G_STAGE, SB = SA + 32768;
#pragma unroll
        for (int kk = 0; kk < 4; kk++) {
            const int g = 2 * kk + (lane >> 4);
            uint32_t af[4][4];
#pragma unroll
            for (int mt = 0; mt < 4; mt++) {
                const int r = 64 * wm + 16 * mt + (lane & 15);
                ldsm4(af[mt], SA + r * 128 + ((g ^ (r & 7)) << 4));
            }
#pragma unroll
            for (int ntp = 0; ntp < 2; ntp++) {
                uint32_t bf[4];
                const int r = 32 * wn + 16 * ntp + (lane & 15);
                ldsm4(bf, SB + r * 128 + ((g ^ (r & 7)) << 4));
#pragma unroll
                for (int mt = 0; mt < 4; mt++) {
                    mma16816(c[mt][2*ntp],   af[mt], bf[0], bf[2]);
                    mma16816(c[mt][2*ntp+1], af[mt], bf[1], bf[3]);
                }
            }
        }
    }

#pragma unroll
    for (int mt = 0; mt < 4; mt++)
#pragma unroll
        for (int nt = 0; nt < 4; nt++) {
            const int n0 = colBase + 32 * wn + 8 * nt + (lane & 3) * 2;
            const float b0v = bias[n0], b1v = bias[n0 + 1];
#pragma unroll
            for (int h = 0; h < 2; h++) {
                const int m = rowBase + 64 * wm + 16 * mt + 8 * h + (lane >> 2);
                float v0 = c[mt][nt][2*h]   + b0v;
                float v1 = c[mt][nt][2*h+1] + b1v;
                if (MODE == 1) {
                    v0 *= scale; v1 *= scale;
                    const uint32_t hi = pack_hf2(v1, v0);
                    const float f0 = __half2float(__ushort_as_half((unsigned short)(hi & 0xffff)));
                    const float f1 = __half2float(__ushort_as_half((unsigned short)(hi >> 16)));
                    const uint32_t lo = pack_hf2(v1 - f1, v0 - f0);
                    const int bb = m >> 11, l = m & (L_ - 1);
                    const int hh = n0 >> 6, d = n0 & (HD_ - 1);
                    const size_t idx = ((size_t)(bb * H_ + hh) * L_ + l) * HD_ + d;
                    *(uint32_t*)((char*)OutH + idx * 2) = hi;
                    *(uint32_t*)((char*)OutL + idx * 2) = lo;
                } else {
                    float2 v = {v0, v1};
                    *(float2*)(OutF + (size_t)m * D_ + n0) = v;
                }
            }
        }
}

__global__ __launch_bounds__(512, 1)
void gemm_proj(const __half* __restrict__ Abase, const __half* __restrict__ WtBase,
               const float* __restrict__ bq, const float* __restrict__ bk,
               const float* __restrict__ bv,
               __half* __restrict__ QKVh, __half* __restrict__ QKVl)
{
    const int z = blockIdx.z;
    const __half* A  = Abase  + (size_t)z * MROWS * KSPLIT;
    const __half* Bt = WtBase + (size_t)z * D_ * KB_;
    const float* bias = (z == 0) ? bq : (z == 1) ? bk : bv;
    gemm_core<1>(A, Bt, bias, nullptr, QKVh + (size_t)z * HSZ, QKVl + (size_t)z * HSZ,
                 (z == 0) ? 0.125f : 1.0f);
}

__global__ __launch_bounds__(512, 1)
void gemm_out(const __half* __restrict__ A, const __half* __restrict__ Bt,
              const float* __restrict__ bias, float* __restrict__ Out)
{
    gemm_core<0>(A, Bt, bias, Out, nullptr, nullptr, 1.0f);
}

// ============================================================================
// Flash attention fp16: CTA = 64 q-rows, 128 thr / 4 warps (warp = 16 rows).
// S = qh.kh + ql.kh ; O += P.vh + P.vl  (P single fp16, built in registers)
// SMEM: Qh,Ql [64][64] = 16KB; Kh,Vh,Vl [2][64][64] = 48KB  -> 64KB, 3 CTA/SM
// ============================================================================
#define ATTN_SMEM 65536

__global__ __launch_bounds__(128, 3)
void attn_mma(const __half* __restrict__ Qh, const __half* __restrict__ Ql,
              const __half* __restrict__ Kh,
              const __half* __restrict__ Vh, const __half* __restrict__ Vl,
              __half* __restrict__ Aout)
{
    extern __shared__ __align__(128) char smem[];
    const uint32_t sb = smem_u32(smem);
    const int tid = threadIdx.x, lane = tid & 31, w = tid >> 5;
    const int q0 = blockIdx.x * 64;
    const int bh = blockIdx.y;
    const size_t base = (size_t)bh * L_ * HD_;

    const uint32_t QHs = sb, QLs = sb + 8192;
    const uint32_t KHs = sb + 16384;            // 2 stages x 8KB
    const uint32_t VHs = sb + 32768;
    const uint32_t VLs = sb + 49152;

    const int lr = tid >> 3, lg = tid & 7;      // row 0..15, granule 0..7

    // Q tiles: 2 arrays x 64 rows
#pragma unroll
    for (int a = 0; a < 2; a++)
#pragma unroll
        for (int j = 0; j < 4; j++) {
            const int r = 16 * j + lr;
            cp16((a ? QLs : QHs) + r * 128 + ((lg ^ (r & 7)) << 4),
                 (a ? Ql : Qh) + base + (size_t)(q0 + r) * HD_ + lg * 8);
        }
    auto issueKV = [&](int t, int s) {
        const uint32_t bases[3] = {KHs + s * 8192, VHs + s * 8192, VLs + s * 8192};
        const __half* srcs[3] = {Kh, Vh, Vl};
#pragma unroll
        for (int a = 0; a < 3; a++)
#pragma unroll
            for (int j = 0; j < 4; j++) {
                const int r = 16 * j + lr;
                cp16(bases[a] + r * 128 + ((lg ^ (r & 7)) << 4),
                     srcs[a] + base + (size_t)(t * 64 + r) * HD_ + lg * 8);
            }
    };
    issueKV(0, 0);
    CPCOMMIT();
    CPWAIT(0);
    __syncthreads();

    // hoist Q fragments (persist whole kernel)
    uint32_t qhf[4][4], qlf[4][4];
#pragma unroll
    for (int kk = 0; kk < 4; kk++) {
        const int g = 2 * kk + (lane >> 4);
        const int r = 16 * w + (lane & 15);
        const uint32_t off = r * 128 + ((g ^ (r & 7)) << 4);
        ldsm4(qhf[kk], QHs + off);
        ldsm4(qlf[kk], QLs + off);
    }

    float o[8][4];
#pragma unroll
    for (int j = 0; j < 8; j++)
#pragma unroll
        for (int k = 0; k < 4; k++) o[j][k] = 0.f;
    float mrow[2] = {-1e30f, -1e30f};
    float lrow[2] = {0.f, 0.f};

    for (int t = 0; t < 32; t++) {
        __syncthreads();
        if (t + 1 < 32) issueKV(t + 1, (t + 1) & 1);
        CPCOMMIT();
        CPWAIT(1);
        __syncthreads();
        const int s = t & 1;
        const uint32_t kh_b = KHs + s * 8192;
        const uint32_t vh_b = VHs + s * 8192, vl_b = VLs + s * 8192;

        // ---- S = Qh.Kh^T + Ql.Kh^T ----
        float sc[8][4];
#pragma unroll
        for (int j = 0; j < 8; j++)
#pragma unroll
            for (int k = 0; k < 4; k++) sc[j][k] = 0.f;

#pragma unroll
        for (int kk = 0; kk < 4; kk++) {
            const int g = 2 * kk + (lane >> 4);
#pragma unroll
            for (int ntp = 0; ntp < 4; ntp++) {
                const int r = 16 * ntp + (lane & 15);
                const uint32_t off = r * 128 + ((g ^ (r & 7)) << 4);
                uint32_t khf[4];
                ldsm4(khf, kh_b + off);
                mma16816(sc[2*ntp],   qhf[kk], khf[0], khf[2]);
                mma16816(sc[2*ntp+1], qhf[kk], khf[1], khf[3]);
                mma16816(sc[2*ntp],   qlf[kk], khf[0], khf[2]);
                mma16816(sc[2*ntp+1], qlf[kk], khf[1], khf[3]);
            }
        }

        // ---- online softmax ----
#pragma unroll
        for (int h = 0; h < 2; h++) {
            float tm = -1e30f;
#pragma unroll
            for (int nt = 0; nt < 8; nt++)
                tm = fmaxf(tm, fmaxf(sc[nt][2*h], sc[nt][2*h+1]));
            tm = fmaxf(tm, __shfl_xor_sync(0xffffffffu, tm, 1));
            tm = fmaxf(tm, __shfl_xor_sync(0xffffffffu, tm, 2));
            const float mn = fmaxf(mrow[h], tm);
            const float corr = __expf(mrow[h] - mn);
            mrow[h] = mn;
            float rs = 0.f;
#pragma unroll
            for (int nt = 0; nt < 8; nt++) {
                const float p0 = __expf(sc[nt][2*h]   - mn);
                const float p1 = __expf(sc[nt][2*h+1] - mn);
                sc[nt][2*h] = p0; sc[nt][2*h+1] = p1;
                rs += p0 + p1;
            }
            rs += __shfl_xor_sync(0xffffffffu, rs, 1);
            rs += __shfl_xor_sync(0xffffffffu, rs, 2);
            lrow[h] = lrow[h] * corr + rs;
#pragma unroll
            for (int nt = 0; nt < 8; nt++) {
                o[nt][2*h]   *= corr;
                o[nt][2*h+1] *= corr;
            }
        }

        // ---- O += P.Vh + P.Vl (P packed fp16 in registers) ----
#pragma unroll
        for (int kk = 0; kk < 4; kk++) {
            uint32_t pa[4];
            {
                const float* s0 = sc[2*kk];
                const float* s1 = sc[2*kk+1];
                pa[0] = pack_hf2(s0[1], s0[0]);
                pa[1] = pack_hf2(s0[3], s0[2]);
                pa[2] = pack_hf2(s1[1], s1[0]);
                pa[3] = pack_hf2(s1[3], s1[2]);
            }
#pragma unroll
            for (int ntp = 0; ntp < 4; ntp++) {
                const int kr = 16 * kk + ((lane >> 3) & 1) * 8 + (lane & 7);
                const int g = 2 * ntp + (lane >> 4);
                const uint32_t off = kr * 128 + ((g ^ (kr & 7)) << 4);
                uint32_t vhf[4], vlf[4];
                ldsm4t(vhf, vh_b + off);
                ldsm4t(vlf, vl_b + off);
                mma16816(o[2*ntp],   pa, vhf[0], vhf[1]);
                mma16816(o[2*ntp+1], pa, vhf[2], vhf[3]);
                mma16816(o[2*ntp],   pa, vlf[0], vlf[1]);
                mma16816(o[2*ntp+1], pa, vlf[2], vlf[3]);
            }
        }
    }

    // ---- epilogue: normalize, fp16 hi/lo split straight into A buffer ----
    const int b = bh >> 4, head = bh & 15;
#pragma unroll
    for (int h = 0; h < 2; h++) {
        const float inv = 1.f / lrow[h];
        const int qr = q0 + 16 * w + 8 * h + (lane >> 2);
        const int m = b * L_ + qr;
        __half* rowp = Aout + (size_t)m * KSPLIT + head * HD_ + (lane & 3) * 2;
#pragma unroll
        for (int nt = 0; nt < 8; nt++) {
            const float v0 = o[nt][2*h]   * inv;
            const float v1 = o[nt][2*h+1] * inv;
            const uint32_t hi = pack_hf2(v1, v0);
            const float f0 = __half2float(__ushort_as_half((unsigned short)(hi & 0xffff)));
            const float f1 = __half2float(__ushort_as_half((unsigned short)(hi >> 16)));
            const uint32_t lo = pack_hf2(v1 - f1, v0 - f0);
            char* p = (char*)(rowp + 8 * nt);
            *(uint32_t*)(p)                   = hi;   // cols [0,1024): hi
            *(uint32_t*)(p + (size_t)D_ * 2)  = lo;   // cols [1024,2048): lo
        }
    }
}

// ============================================================================
// launch
// ============================================================================
extern "C" void kernel_launch(void* const* d_in, const int* in_sizes, int n_in,
                              void* d_out, int out_size)
{
    const float* query = (const float*)d_in[0];
    const float* key_  = (const float*)d_in[1];
    const float* value = (const float*)d_in[2];
    const float* Wq = (const float*)d_in[3];
    const float* bq = (const float*)d_in[4];
    const float* Wk = (const float*)d_in[5];
    const float* bk = (const float*)d_in[6];
    const float* Wv = (const float*)d_in[7];
    const float* bv = (const float*)d_in[8];
    const float* Wo = (const float*)d_in[9];
    const float* bo = (const float*)d_in[10];
    float* out = (float*)d_out;

    __half *Ab, *Wt, *QKVh, *QKVl;
    cudaGetSymbolAddress((void**)&Ab,   g_A);
    cudaGetSymbolAddress((void**)&Wt,   g_Wt);
    cudaGetSymbolAddress((void**)&QKVh, g_QKVh);
    cudaGetSymbolAddress((void**)&QKVl, g_QKVl);

    cudaFuncSetAttribute(gemm_proj, cudaFuncAttributeMaxDynamicSharedMemorySize, G_SMEM);
    cudaFuncSetAttribute(gemm_out,  cudaFuncAttributeMaxDynamicSharedMemorySize, G_SMEM);
    cudaFuncSetAttribute(attn_mma,  cudaFuncAttributeMaxDynamicSharedMemorySize, ATTN_SMEM);

    // 1. weight conversion (batched z=4)
    dim3 wg(32, 32, 4), wb(32, 8);
    split_weightT4<<<wg, wb>>>(Wq, Wk, Wv, Wo, Wt);

    // 2. input splits (batched z=3)
    dim3 sg(MROWS * D_ / 1024, 3);
    split_rows3<<<sg, 256>>>(query, key_, value, Ab);

    // 3. q/k/v projections (batched z=3)
    dim3 gg(D_ / 128, MROWS / 256, 3);
    gemm_proj<<<gg, 512, G_SMEM>>>(Ab, Wt, bq, bk, bv, QKVh, QKVl);

    // 4. attention (writes split A for the output GEMM directly)
    dim3 ag(L_ / 64, B_ * H_);    // (32, 32) = 1024 CTAs
    attn_mma<<<ag, 128, ATTN_SMEM>>>(QKVh, QKVl,
                                     QKVh + (size_t)1 * HSZ,
                                     QKVh + (size_t)2 * HSZ, QKVl + (size_t)2 * HSZ,
                                     Ab);

    // 5. output projection
    dim3 og(D_ / 128, MROWS / 256);
    gemm_out<<<og, 512, G_SMEM>>>(Ab, Wt + (size_t)3 * D_ * KB_, bo, out);
}

// round 6
// speedup vs baseline: 1.8375x; 1.2026x over previous
#include <cuda_runtime.h>
#include <cuda_fp16.h>
#include <cstdint>

#define B_  2
#define L_  2048
#define D_  1024
#define H_  16
#define HD_ 64
#define MROWS 4096
#define KSPLIT 2048        // A' = [xh | xl] fp16
#define KB_ 1024           // B' = wh only (reused for both halves)
#define HSZ (B_ * H_ * L_ * HD_)

// Q pre-scale: 1/sqrt(64) * log2(e)  (softmax runs in log2 domain)
#define QSCALE 0.18033688011112042f

// ---------------- scratch (static device globals; no allocation allowed) ----
__device__ __half g_A[3][MROWS * KSPLIT];   // split activations; [0] reused for attn-out
__device__ __half g_Wt[4][D_ * KB_];        // transposed weight hi
__device__ __half g_QKV[3][HSZ];            // q/k/v fp16 [B,H,L,HD] (single-term)

// ============================================================================
// helpers
// ============================================================================
__device__ __forceinline__ uint32_t smem_u32(const void* p) {
    uint32_t a;
    asm("{ .reg .u64 t; cvta.to.shared.u64 t, %1; cvt.u32.u64 %0, t; }" : "=r"(a) : "l"(p));
    return a;
}
__device__ __forceinline__ void cp16(uint32_t dst, const void* src) {
    asm volatile("cp.async.cg.shared.global [%0], [%1], 16;" :: "r"(dst), "l"(src));
}
#define CPCOMMIT() asm volatile("cp.async.commit_group;" ::: "memory")
#define CPWAIT(n)  asm volatile("cp.async.wait_group %0;" :: "n"(n) : "memory")

__device__ __forceinline__ void ldsm4(uint32_t r[4], uint32_t addr) {
    asm volatile("ldmatrix.sync.aligned.m8n8.x4.shared.b16 {%0,%1,%2,%3}, [%4];"
        : "=r"(r[0]), "=r"(r[1]), "=r"(r[2]), "=r"(r[3]) : "r"(addr));
}
__device__ __forceinline__ void ldsm4t(uint32_t r[4], uint32_t addr) {
    asm volatile("ldmatrix.sync.aligned.m8n8.x4.trans.shared.b16 {%0,%1,%2,%3}, [%4];"
        : "=r"(r[0]), "=r"(r[1]), "=r"(r[2]), "=r"(r[3]) : "r"(addr));
}
__device__ __forceinline__ void mma16816(float c[4], const uint32_t a[4],
                                         uint32_t b0, uint32_t b1) {
    asm volatile("mma.sync.aligned.m16n8k16.row.col.f32.f16.f16.f32 "
        "{%0,%1,%2,%3}, {%4,%5,%6,%7}, {%8,%9}, {%0,%1,%2,%3};"
        : "+f"(c[0]), "+f"(c[1]), "+f"(c[2]), "+f"(c[3])
        : "r"(a[0]), "r"(a[1]), "r"(a[2]), "r"(a[3]), "r"(b0), "r"(b1));
}
__device__ __forceinline__ uint32_t pack_hf2(float hiVal, float loVal) {
    uint32_t r;
    asm("cvt.rn.f16x2.f32 %0, %1, %2;" : "=r"(r) : "f"(hiVal), "f"(loVal));
    return r;
}

// ============================================================================
// batched split conversions (fp16 2-term for GEMM A operands)
// ============================================================================
__global__ void split_rows3(const float* __restrict__ X0, const float* __restrict__ X1,
                            const float* __restrict__ X2, __half* __restrict__ Abase)
{
    const int z = blockIdx.y;
    const float* X = (z == 0) ? X0 : (z == 1) ? X1 : X2;
    __half* A = Abase + (size_t)z * MROWS * KSPLIT;
    const int idx = blockIdx.x * 256 + threadIdx.x;
    const int r = idx >> 8;
    const int c = (idx & 255) << 2;
    float4 v = *(const float4*)(X + (size_t)r * D_ + c);
    float vf[4] = {v.x, v.y, v.z, v.w};
    ushort4 hv, lv;
    unsigned short* hp = &hv.x;
    unsigned short* lp = &lv.x;
#pragma unroll
    for (int j = 0; j < 4; j++) {
        __half hi = __float2half(vf[j]);
        __half lo = __float2half(vf[j] - __half2float(hi));
        hp[j] = __half_as_ushort(hi);
        lp[j] = __half_as_ushort(lo);
    }
    __half* row = A + (size_t)r * KSPLIT;
    *(ushort4*)(row + c)      = hv;
    *(ushort4*)(row + D_ + c) = lv;
}

__global__ void split_weightT4(const float* __restrict__ W0, const float* __restrict__ W1,
                               const float* __restrict__ W2, const float* __restrict__ W3,
                               __half* __restrict__ WtBase)
{
    __shared__ float t[32][33];
    const int z = blockIdx.z;
    const float* W = (z == 0) ? W0 : (z == 1) ? W1 : (z == 2) ? W2 : W3;
    __half* Wt = WtBase + (size_t)z * D_ * KB_;
    const int k0 = blockIdx.x * 32, n0 = blockIdx.y * 32;
    const int tx = threadIdx.x, ty = threadIdx.y;
    for (int i = ty; i < 32; i += 8)
        t[i][tx] = W[(size_t)(k0 + i) * D_ + n0 + tx];
    __syncthreads();
    for (int i = ty; i < 32; i += 8)
        Wt[(size_t)(n0 + i) * KB_ + k0 + tx] = __float2half(t[tx][i]);
}

// ============================================================================
// fp16 mma GEMM: C = A'[M,2048] x Wt[N,1024]^T (B reused for both K-halves)
// CTA 256x128, 512 threads, warp 64x32, 4-stage cp.async, 32 K-chunks of 64.
// ============================================================================
#define G_STAGE 49152
#define G_SMEM  (4 * G_STAGE)     // 196608

template <int MODE>   // 0: fp32 [M,D] out, 1: fp16 single head-layout out
__device__ __forceinline__
void gemm_core(const __half* __restrict__ A, const __half* __restrict__ Bt,
               const float* __restrict__ bias, float* __restrict__ OutF,
               __half* __restrict__ OutH, float scale)
{
    extern __shared__ __align__(128) char smem[];
    const uint32_t sb = smem_u32(smem);
    const int tid = threadIdx.x, lane = tid & 31, warp = tid >> 5;
    const int wm = warp >> 2, wn = warp & 3;
    const int rowBase = blockIdx.y * 256;
    const int colBase = blockIdx.x * 128;

    float c[4][4][4];
#pragma unroll
    for (int i = 0; i < 4; i++)
#pragma unroll
        for (int j = 0; j < 4; j++)
#pragma unroll
            for (int k = 0; k < 4; k++) c[i][j][k] = 0.f;

    const int lr = tid >> 3, lg = tid & 7;

    auto issue = [&](int chunk, int s) {
        const uint32_t SA = sb + s * G_STAGE, SB = SA + 32768;
        const int ca = chunk * 64;
        const int cb = (chunk & 15) * 64;
#pragma unroll
        for (int j = 0; j < 4; j++) {
            const int r = 64 * j + lr;
            cp16(SA + r * 128 + ((lg ^ (r & 7)) << 4),
                 A + (size_t)(rowBase + r) * KSPLIT + ca + lg * 8);
        }
#pragma unroll
        for (int j = 0; j < 2; j++) {
            const int r = 64 * j + lr;
            cp16(SB + r * 128 + ((lg ^ (r & 7)) << 4),
                 Bt + (size_t)(colBase + r) * KB_ + cb + lg * 8);
        }
    };

    issue(0, 0); CPCOMMIT();
    issue(1, 1); CPCOMMIT();
    issue(2, 2); CPCOMMIT();

    for (int ch = 0; ch < 32; ch++) {
        __syncthreads();
        if (ch + 3 < 32) issue(ch + 3, (ch + 3) & 3);
        CPCOMMIT();
        CPWAIT(3);
        __syncthreads();

        const uint32_t SA = sb + (ch & 3) * G_STAGE, SB = SA + 32768;
#pragma unroll
        for (int kk = 0; kk < 4; kk++) {
            const int g = 2 * kk + (lane >> 4);
            uint32_t af[4][4];
#pragma unroll
            for (int mt = 0; mt < 4; mt++) {
                const int r = 64 * wm + 16 * mt + (lane & 15);
                ldsm4(af[mt], SA + r * 128 + ((g ^ (r & 7)) << 4));
            }
#pragma unroll
            for (int ntp = 0; ntp < 2; ntp++) {
                uint32_t bf[4];
                const int r = 32 * wn + 16 * ntp + (lane & 15);
                ldsm4(bf, SB + r * 128 + ((g ^ (r & 7)) << 4));
#pragma unroll
                for (int mt = 0; mt < 4; mt++) {
                    mma16816(c[mt][2*ntp],   af[mt], bf[0], bf[2]);
                    mma16816(c[mt][2*ntp+1], af[mt], bf[1], bf[3]);
                }
            }
        }
    }

#pragma unroll
    for (int mt = 0; mt < 4; mt++)
#pragma unroll
        for (int nt = 0; nt < 4; nt++) {
            const int n0 = colBase + 32 * wn + 8 * nt + (lane & 3) * 2;
            const float b0v = bias[n0], b1v = bias[n0 + 1];
#pragma unroll
            for (int h = 0; h < 2; h++) {
                const int m = rowBase + 64 * wm + 16 * mt + 8 * h + (lane >> 2);
                float v0 = c[mt][nt][2*h]   + b0v;
                float v1 = c[mt][nt][2*h+1] + b1v;
                if (MODE == 1) {
                    const uint32_t hi = pack_hf2(v1 * scale, v0 * scale);
                    const int bb = m >> 11, l = m & (L_ - 1);
                    const int hh = n0 >> 6, d = n0 & (HD_ - 1);
                    const size_t idx = ((size_t)(bb * H_ + hh) * L_ + l) * HD_ + d;
                    *(uint32_t*)((char*)OutH + idx * 2) = hi;
                } else {
                    float2 v = {v0, v1};
                    *(float2*)(OutF + (size_t)m * D_ + n0) = v;
                }
            }
        }
}

__global__ __launch_bounds__(512, 1)
void gemm_proj(const __half* __restrict__ Abase, const __half* __restrict__ WtBase,
               const float* __restrict__ bq, const float* __restrict__ bk,
               const float* __restrict__ bv, __half* __restrict__ QKV)
{
    const int z = blockIdx.z;
    const __half* A  = Abase  + (size_t)z * MROWS * KSPLIT;
    const __half* Bt = WtBase + (size_t)z * D_ * KB_;
    const float* bias = (z == 0) ? bq : (z == 1) ? bk : bv;
    gemm_core<1>(A, Bt, bias, nullptr, QKV + (size_t)z * HSZ,
                 (z == 0) ? QSCALE : 1.0f);
}

__global__ __launch_bounds__(512, 1)
void gemm_out(const __half* __restrict__ A, const __half* __restrict__ Bt,
              const float* __restrict__ bias, float* __restrict__ Out)
{
    gemm_core<0>(A, Bt, bias, Out, nullptr, 1.0f);
}

// ============================================================================
// Flash attention fp16 single-term: CTA = 64 q-rows, 128 thr / 4 warps.
// S = q.k (log2 domain, Q pre-scaled by 0.125*log2e); P = exp2(S - max);
// O += P.v. SMEM: Q [64][64] 8KB + K,V 2 stages x 8KB each = 40KB -> 4 CTA/SM
// ============================================================================
#define ATTN_SMEM 40960

__global__ __launch_bounds__(128, 4)
void attn_mma(const __half* __restrict__ Qg, const __half* __restrict__ Kg,
              const __half* __restrict__ Vg, __half* __restrict__ Aout)
{
    extern __shared__ __align__(128) char smem[];
    const uint32_t sb = smem_u32(smem);
    const int tid = threadIdx.x, lane = tid & 31, w = tid >> 5;
    const int q0 = blockIdx.x * 64;
    const int bh = blockIdx.y;
    const size_t base = (size_t)bh * L_ * HD_;

    const uint32_t QHs = sb;
    const uint32_t KHs = sb + 8192;      // 2 stages x 8KB: [8192, 24576)
    const uint32_t VHs = sb + 24576;     // 2 stages x 8KB: [24576, 40960)

    const int lr = tid >> 3, lg = tid & 7;

    // Q tile
#pragma unroll
    for (int j = 0; j < 4; j++) {
        const int r = 16 * j + lr;
        cp16(QHs + r * 128 + ((lg ^ (r & 7)) << 4),
             Qg + base + (size_t)(q0 + r) * HD_ + lg * 8);
    }
    auto issueKV = [&](int t, int s) {
#pragma unroll
        for (int a = 0; a < 2; a++) {
            const uint32_t dstB = (a ? VHs : KHs) + s * 8192;
            const __half* src = (a ? Vg : Kg) + base + (size_t)(t * 64) * HD_;
#pragma unroll
            for (int j = 0; j < 4; j++) {
                const int r = 16 * j + lr;
                cp16(dstB + r * 128 + ((lg ^ (r & 7)) << 4),
                     src + (size_t)r * HD_ + lg * 8);
            }
        }
    };
    issueKV(0, 0);
    CPCOMMIT();
    CPWAIT(0);
    __syncthreads();

    // hoist Q fragments (persist whole kernel)
    uint32_t qf[4][4];
#pragma unroll
    for (int kk = 0; kk < 4; kk++) {
        const int g = 2 * kk + (lane >> 4);
        const int r = 16 * w + (lane & 15);
        ldsm4(qf[kk], QHs + r * 128 + ((g ^ (r & 7)) << 4));
    }

    float o[8][4];
#pragma unroll
    for (int j = 0; j < 8; j++)
#pragma unroll
        for (int k = 0; k < 4; k++) o[j][k] = 0.f;
    float mrow[2] = {-1e30f, -1e30f};
    float lrow[2] = {0.f, 0.f};

    for (int t = 0; t < 32; t++) {
        __syncthreads();
        if (t + 1 < 32) issueKV(t + 1, (t + 1) & 1);
        CPCOMMIT();
        CPWAIT(1);
        __syncthreads();
        const int s = t & 1;
        const uint32_t kh_b = KHs + s * 8192;
        const uint32_t vh_b = VHs + s * 8192;

        // ---- S = Q.K^T (log2 domain) ----
        float sc[8][4];
#pragma unroll
        for (int j = 0; j < 8; j++)
#pragma unroll
            for (int k = 0; k < 4; k++) sc[j][k] = 0.f;

#pragma unroll
        for (int kk = 0; kk < 4; kk++) {
            const int g = 2 * kk + (lane >> 4);
#pragma unroll
            for (int ntp = 0; ntp < 4; ntp++) {
                const int r = 16 * ntp + (lane & 15);
                uint32_t khf[4];
                ldsm4(khf, kh_b + r * 128 + ((g ^ (r & 7)) << 4));
                mma16816(sc[2*ntp],   qf[kk], khf[0], khf[2]);
                mma16816(sc[2*ntp+1], qf[kk], khf[1], khf[3]);
            }
        }

        // ---- online softmax (exp2; ballot-guarded rescale) ----
#pragma unroll
        for (int h = 0; h < 2; h++) {
            float tm = -1e30f;
#pragma unroll
            for (int nt = 0; nt < 8; nt++)
                tm = fmaxf(tm, fmaxf(sc[nt][2*h], sc[nt][2*h+1]));
            tm = fmaxf(tm, __shfl_xor_sync(0xffffffffu, tm, 1));
            tm = fmaxf(tm, __shfl_xor_sync(0xffffffffu, tm, 2));
            const float mo = mrow[h];
            const float mn = fmaxf(mo, tm);
            mrow[h] = mn;
            float rs = 0.f;
#pragma unroll
            for (int nt = 0; nt < 8; nt++) {
                const float p0 = exp2f(sc[nt][2*h]   - mn);
                const float p1 = exp2f(sc[nt][2*h+1] - mn);
                sc[nt][2*h] = p0; sc[nt][2*h+1] = p1;
                rs += p0 + p1;
            }
            rs += __shfl_xor_sync(0xffffffffu, rs, 1);
            rs += __shfl_xor_sync(0xffffffffu, rs, 2);
            if (__ballot_sync(0xffffffffu, mn != mo)) {
                const float corr = exp2f(mo - mn);
                lrow[h] = lrow[h] * corr + rs;
#pragma unroll
                for (int nt = 0; nt < 8; nt++) {
                    o[nt][2*h]   *= corr;
                    o[nt][2*h+1] *= corr;
                }
            } else {
                lrow[h] += rs;
            }
        }

        // ---- O += P.V (P packed fp16 in registers) ----
#pragma unroll
        for (int kk = 0; kk < 4; kk++) {
            uint32_t pa[4];
            {
                const float* s0 = sc[2*kk];
                const float* s1 = sc[2*kk+1];
                pa[0] = pack_hf2(s0[1], s0[0]);
                pa[1] = pack_hf2(s0[3], s0[2]);
                pa[2] = pack_hf2(s1[1], s1[0]);
                pa[3] = pack_hf2(s1[3], s1[2]);
            }
#pragma unroll
            for (int ntp = 0; ntp < 4; ntp++) {
                const int kr = 16 * kk + ((lane >> 3) & 1) * 8 + (lane & 7);
                const int g = 2 * ntp + (lane >> 4);
                uint32_t vhf[4];
                ldsm4t(vhf, vh_b + kr * 128 + ((g ^ (kr & 7)) << 4));
                mma16816(o[2*ntp],   pa, vhf[0], vhf[1]);
                mma16816(o[2*ntp+1], pa, vhf[2], vhf[3]);
            }
        }
    }

    // ---- epilogue: normalize, fp16 hi/lo split straight into A buffer ----
    const int b = bh >> 4, head = bh & 15;
#pragma unroll
    for (int h = 0; h < 2; h++) {
        const float inv = 1.f / lrow[h];
        const int qr = q0 + 16 * w + 8 * h + (lane >> 2);
        const int m = b * L_ + qr;
        __half* rowp = Aout + (size_t)m * KSPLIT + head * HD_ + (lane & 3) * 2;
#pragma unroll
        for (int nt = 0; nt < 8; nt++) {
            const float v0 = o[nt][2*h]   * inv;
            const float v1 = o[nt][2*h+1] * inv;
            const uint32_t hi = pack_hf2(v1, v0);
            const float f0 = __half2float(__ushort_as_half((unsigned short)(hi & 0xffff)));
            const float f1 = __half2float(__ushort_as_half((unsigned short)(hi >> 16)));
            const uint32_t lo = pack_hf2(v1 - f1, v0 - f0);
            char* p = (char*)(rowp + 8 * nt);
            *(uint32_t*)(p)                   = hi;   // cols [0,1024): hi
            *(uint32_t*)(p + (size_t)D_ * 2)  = lo;   // cols [1024,2048): lo
        }
    }
}

// ============================================================================
// launch
// ============================================================================
extern "C" void kernel_launch(void* const* d_in, const int* in_sizes, int n_in,
                              void* d_out, int out_size)
{
    const float* query = (const float*)d_in[0];
    const float* key_  = (const float*)d_in[1];
    const float* value = (const float*)d_in[2];
    const float* Wq = (const float*)d_in[3];
    const float* bq = (const float*)d_in[4];
    const float* Wk = (const float*)d_in[5];
    const float* bk = (const float*)d_in[6];
    const float* Wv = (const float*)d_in[7];
    const float* bv = (const float*)d_in[8];
    const float* Wo = (const float*)d_in[9];
    const float* bo = (const float*)d_in[10];
    float* out = (float*)d_out;

    __half *Ab, *Wt, *QKV;
    cudaGetSymbolAddress((void**)&Ab,  g_A);
    cudaGetSymbolAddress((void**)&Wt,  g_Wt);
    cudaGetSymbolAddress((void**)&QKV, g_QKV);

    cudaFuncSetAttribute(gemm_proj, cudaFuncAttributeMaxDynamicSharedMemorySize, G_SMEM);
    cudaFuncSetAttribute(gemm_out,  cudaFuncAttributeMaxDynamicSharedMemorySize, G_SMEM);
    cudaFuncSetAttribute(attn_mma,  cudaFuncAttributeMaxDynamicSharedMemorySize, ATTN_SMEM);

    // 1. weight conversion (batched z=4)
    dim3 wg(32, 32, 4), wb(32, 8);
    split_weightT4<<<wg, wb>>>(Wq, Wk, Wv, Wo, Wt);

    // 2. input splits (batched z=3)
    dim3 sg(MROWS * D_ / 1024, 3);
    split_rows3<<<sg, 256>>>(query, key_, value, Ab);

    // 3. q/k/v projections (batched z=3)
    dim3 gg(D_ / 128, MROWS / 256, 3);
    gemm_proj<<<gg, 512, G_SMEM>>>(Ab, Wt, bq, bk, bv, QKV);

    // 4. attention (writes split A for the output GEMM directly)
    dim3 ag(L_ / 64, B_ * H_);    // (32, 32) = 1024 CTAs
    attn_mma<<<ag, 128, ATTN_SMEM>>>(QKV, QKV + (size_t)1 * HSZ,
                                     QKV + (size_t)2 * HSZ, Ab);

    // 5. output projection
    dim3 og(D_ / 128, MROWS / 256);
    gemm_out<<<og, 512, G_SMEM>>>(Ab, Wt + (size_t)3 * D_ * KB_, bo, out);
}

// round 7
// speedup vs baseline: 2.5955x; 1.4125x over previous
#include <cuda_runtime.h>
#include <cuda_fp16.h>
#include <cstdint>

#define B_  2
#define L_  2048
#define D_  1024
#define H_  16
#define HD_ 64
#define MROWS 4096
#define KA_ 1024
#define HSZ (B_ * H_ * L_ * HD_)

// Q pre-scale: 1/sqrt(64) * log2(e)  (softmax runs in log2 domain)
#define QSCALE 0.18033688011112042f

// ---------------- scratch (static device globals; no allocation allowed) ----
__device__ __half g_A[3][MROWS * KA_];      // fp16 activations; [0] reused for attn-out
__device__ __half g_Wt[4][D_ * KA_];        // transposed fp16 weights
__device__ __half g_QKV[3][HSZ];            // q/k/v fp16 [B,H,L,HD]

// ============================================================================
// helpers
// ============================================================================
__device__ __forceinline__ uint32_t smem_u32(const void* p) {
    uint32_t a;
    asm("{ .reg .u64 t; cvta.to.shared.u64 t, %1; cvt.u32.u64 %0, t; }" : "=r"(a) : "l"(p));
    return a;
}
__device__ __forceinline__ void cp16(uint32_t dst, const void* src) {
    asm volatile("cp.async.cg.shared.global [%0], [%1], 16;" :: "r"(dst), "l"(src));
}
#define CPCOMMIT() asm volatile("cp.async.commit_group;" ::: "memory")
#define CPWAIT(n)  asm volatile("cp.async.wait_group %0;" :: "n"(n) : "memory")

__device__ __forceinline__ void ldsm4(uint32_t r[4], uint32_t addr) {
    asm volatile("ldmatrix.sync.aligned.m8n8.x4.shared.b16 {%0,%1,%2,%3}, [%4];"
        : "=r"(r[0]), "=r"(r[1]), "=r"(r[2]), "=r"(r[3]) : "r"(addr));
}
__device__ __forceinline__ void ldsm4t(uint32_t r[4], uint32_t addr) {
    asm volatile("ldmatrix.sync.aligned.m8n8.x4.trans.shared.b16 {%0,%1,%2,%3}, [%4];"
        : "=r"(r[0]), "=r"(r[1]), "=r"(r[2]), "=r"(r[3]) : "r"(addr));
}
__device__ __forceinline__ void mma16816(float c[4], const uint32_t a[4],
                                         uint32_t b0, uint32_t b1) {
    asm volatile("mma.sync.aligned.m16n8k16.row.col.f32.f16.f16.f32 "
        "{%0,%1,%2,%3}, {%4,%5,%6,%7}, {%8,%9}, {%0,%1,%2,%3};"
        : "+f"(c[0]), "+f"(c[1]), "+f"(c[2]), "+f"(c[3])
        : "r"(a[0]), "r"(a[1]), "r"(a[2]), "r"(a[3]), "r"(b0), "r"(b1));
}
__device__ __forceinline__ uint32_t pack_hf2(float hiVal, float loVal) {
    uint32_t r;
    asm("cvt.rn.f16x2.f32 %0, %1, %2;" : "=r"(r) : "f"(hiVal), "f"(loVal));
    return r;
}

// ============================================================================
// batched conversions (single-term fp16)
// ============================================================================
__global__ void split_rows3(const float* __restrict__ X0, const float* __restrict__ X1,
                            const float* __restrict__ X2, __half* __restrict__ Abase)
{
    const int z = blockIdx.y;
    const float* X = (z == 0) ? X0 : (z == 1) ? X1 : X2;
    __half* A = Abase + (size_t)z * MROWS * KA_;
    const int idx = blockIdx.x * 256 + threadIdx.x;
    float4 v = *(const float4*)(X + (size_t)idx * 4);
    ushort4 hv;
    hv.x = __half_as_ushort(__float2half(v.x));
    hv.y = __half_as_ushort(__float2half(v.y));
    hv.z = __half_as_ushort(__float2half(v.z));
    hv.w = __half_as_ushort(__float2half(v.w));
    *(ushort4*)(A + (size_t)idx * 4) = hv;
}

__global__ void split_weightT4(const float* __restrict__ W0, const float* __restrict__ W1,
                               const float* __restrict__ W2, const float* __restrict__ W3,
                               __half* __restrict__ WtBase)
{
    __shared__ float t[32][33];
    const int z = blockIdx.z;
    const float* W = (z == 0) ? W0 : (z == 1) ? W1 : (z == 2) ? W2 : W3;
    __half* Wt = WtBase + (size_t)z * D_ * KA_;
    const int k0 = blockIdx.x * 32, n0 = blockIdx.y * 32;
    const int tx = threadIdx.x, ty = threadIdx.y;
    for (int i = ty; i < 32; i += 8)
        t[i][tx] = W[(size_t)(k0 + i) * D_ + n0 + tx];
    __syncthreads();
    for (int i = ty; i < 32; i += 8)
        Wt[(size_t)(n0 + i) * KA_ + k0 + tx] = __float2half(t[tx][i]);
}

// ============================================================================
// fp16 mma GEMM: C = A[M,1024] x Wt[N,1024]^T
// CTA 256x128, 512 threads, warp 64x32, 4-stage cp.async, 16 K-chunks of 64.
// ============================================================================
#define G_STAGE 49152
#define G_SMEM  (4 * G_STAGE)     // 196608

template <int MODE>   // 0: fp32 [M,D] out, 1: fp16 head-layout out
__device__ __forceinline__
void gemm_core(const __half* __restrict__ A, const __half* __restrict__ Bt,
               const float* __restrict__ bias, float* __restrict__ OutF,
               __half* __restrict__ OutH, float scale)
{
    extern __shared__ __align__(128) char smem[];
    const uint32_t sb = smem_u32(smem);
    const int tid = threadIdx.x, lane = tid & 31, warp = tid >> 5;
    const int wm = warp >> 2, wn = warp & 3;
    const int rowBase = blockIdx.y * 256;
    const int colBase = blockIdx.x * 128;

    float c[4][4][4];
#pragma unroll
    for (int i = 0; i < 4; i++)
#pragma unroll
        for (int j = 0; j < 4; j++)
#pragma unroll
            for (int k = 0; k < 4; k++) c[i][j][k] = 0.f;

    const int lr = tid >> 3, lg = tid & 7;

    auto issue = [&](int chunk, int s) {
        const uint32_t SA = sb + s * G_STAGE, SB = SA + 32768;
        const int c0 = chunk * 64;
#pragma unroll
        for (int j = 0; j < 4; j++) {
            const int r = 64 * j + lr;
            cp16(SA + r * 128 + ((lg ^ (r & 7)) << 4),
                 A + (size_t)(rowBase + r) * KA_ + c0 + lg * 8);
        }
#pragma unroll
        for (int j = 0; j < 2; j++) {
            const int r = 64 * j + lr;
            cp16(SB + r * 128 + ((lg ^ (r & 7)) << 4),
                 Bt + (size_t)(colBase + r) * KA_ + c0 + lg * 8);
        }
    };

    issue(0, 0); CPCOMMIT();
    issue(1, 1); CPCOMMIT();
    issue(2, 2); CPCOMMIT();

    for (int ch = 0; ch < 16; ch++) {
        __syncthreads();
        if (ch + 3 < 16) issue(ch + 3, (ch + 3) & 3);
        CPCOMMIT();
        CPWAIT(3);
        __syncthreads();

        const uint32_t SA = sb + (ch & 3) * G_STAGE, SB = SA + 32768;
#pragma unroll
        for (int kk = 0; kk < 4; kk++) {
            const int g = 2 * kk + (lane >> 4);
            uint32_t af[4][4];
#pragma unroll
            for (int mt = 0; mt < 4; mt++) {
                const int r = 64 * wm + 16 * mt + (lane & 15);
                ldsm4(af[mt], SA + r * 128 + ((g ^ (r & 7)) << 4));
            }
#pragma unroll
            for (int ntp = 0; ntp < 2; ntp++) {
                uint32_t bf[4];
                const int r = 32 * wn + 16 * ntp + (lane & 15);
                ldsm4(bf, SB + r * 128 + ((g ^ (r & 7)) << 4));
#pragma unroll
                for (int mt = 0; mt < 4; mt++) {
                    mma16816(c[mt][2*ntp],   af[mt], bf[0], bf[2]);
                    mma16816(c[mt][2*ntp+1], af[mt], bf[1], bf[3]);
                }
            }
        }
    }

#pragma unroll
    for (int mt = 0; mt < 4; mt++)
#pragma unroll
        for (int nt = 0; nt < 4; nt++) {
            const int n0 = colBase + 32 * wn + 8 * nt + (lane & 3) * 2;
            const float b0v = bias[n0], b1v = bias[n0 + 1];
#pragma unroll
            for (int h = 0; h < 2; h++) {
                const int m = rowBase + 64 * wm + 16 * mt + 8 * h + (lane >> 2);
                float v0 = c[mt][nt][2*h]   + b0v;
                float v1 = c[mt][nt][2*h+1] + b1v;
                if (MODE == 1) {
                    const uint32_t hi = pack_hf2(v1 * scale, v0 * scale);
                    const int bb = m >> 11, l = m & (L_ - 1);
                    const int hh = n0 >> 6, d = n0 & (HD_ - 1);
                    const size_t idx = ((size_t)(bb * H_ + hh) * L_ + l) * HD_ + d;
                    *(uint32_t*)((char*)OutH + idx * 2) = hi;
                } else {
                    float2 v = {v0, v1};
                    *(float2*)(OutF + (size_t)m * D_ + n0) = v;
                }
            }
        }
}

__global__ __launch_bounds__(512, 1)
void gemm_proj(const __half* __restrict__ Abase, const __half* __restrict__ WtBase,
               const float* __restrict__ bq, const float* __restrict__ bk,
               const float* __restrict__ bv, __half* __restrict__ QKV)
{
    const int z = blockIdx.z;
    const __half* A  = Abase  + (size_t)z * MROWS * KA_;
    const __half* Bt = WtBase + (size_t)z * D_ * KA_;
    const float* bias = (z == 0) ? bq : (z == 1) ? bk : bv;
    gemm_core<1>(A, Bt, bias, nullptr, QKV + (size_t)z * HSZ,
                 (z == 0) ? QSCALE : 1.0f);
}

__global__ __launch_bounds__(512, 1)
void gemm_out(const __half* __restrict__ A, const __half* __restrict__ Bt,
              const float* __restrict__ bias, float* __restrict__ Out)
{
    gemm_core<0>(A, Bt, bias, Out, nullptr, 1.0f);
}

// ============================================================================
// Flash attention fp16: CTA = 64 q-rows, 128 thr / 4 warps (warp = 16 rows).
// Separable-swizzle address precompute, XOR stage toggle.
// SMEM layout (offsets from sb): Q [0,0x2000); K0 [0x2000,0x4000);
// V0 [0x4000,0x6000); K1 [0x6000,0x8000); V1 [0xC000,0xE000). Total 56KB.
// K stage toggle = offset XOR 0x4000, V stage toggle = offset XOR 0x8000.
// ============================================================================
#define ATTN_SMEM 57344

__global__ __launch_bounds__(128, 4)
void attn_mma(const __half* __restrict__ Qg, const __half* __restrict__ Kg,
              const __half* __restrict__ Vg, __half* __restrict__ Aout)
{
    extern __shared__ __align__(128) char smem[];
    const uint32_t sb = smem_u32(smem);
    const int tid = threadIdx.x, lane = tid & 31, w = tid >> 5;
    const int q0 = blockIdx.x * 64;
    const int bh = blockIdx.y;
    const size_t base = (size_t)bh * L_ * HD_;

    const int lr = tid >> 3, lg = tid & 7;

    // Q tile -> [0, 0x2000)
#pragma unroll
    for (int j = 0; j < 4; j++) {
        const int r = 16 * j + lr;
        cp16(sb + r * 128 + ((lg ^ (r & 7)) << 4),
             Qg + base + (size_t)(q0 + r) * HD_ + lg * 8);
    }
    auto issueKV = [&](int t, int s) {
        const uint32_t kb = sb + (s ? 0x6000u : 0x2000u);
        const uint32_t vb = sb + (s ? 0xC000u : 0x4000u);
        const __half* ks = Kg + base + (size_t)(t * 64) * HD_;
        const __half* vs = Vg + base + (size_t)(t * 64) * HD_;
#pragma unroll
        for (int j = 0; j < 4; j++) {
            const int r = 16 * j + lr;
            const uint32_t off = r * 128 + ((lg ^ (r & 7)) << 4);
            cp16(kb + off, ks + (size_t)r * HD_ + lg * 8);
            cp16(vb + off, vs + (size_t)r * HD_ + lg * 8);
        }
    };
    issueKV(0, 0);
    CPCOMMIT();
    CPWAIT(0);
    __syncthreads();

    // separable swizzle pieces (all row indices = lane mod 8)
    uint32_t col[4];             // sb + swizzled column part, indexed by K-granule / V-ntp
#pragma unroll
    for (int i = 0; i < 4; i++)
        col[i] = sb + ((uint32_t)((2 * i + (lane >> 4)) ^ (lane & 7)) << 4);

    // hoisted Q fragments
    uint32_t qf[4][4];
#pragma unroll
    for (int kk = 0; kk < 4; kk++) {
        const uint32_t qrow = (uint32_t)(16 * w + (lane & 15)) * 128;
        ldsm4(qf[kk], col[kk] + qrow);
    }

    uint32_t krow[4], vrow[4];   // stage-resident row offsets (XOR-toggled)
#pragma unroll
    for (int i = 0; i < 4; i++) {
        krow[i] = 0x2000u + (uint32_t)(16 * i + (lane & 15)) * 128;
        vrow[i] = 0x4000u + (uint32_t)(16 * i + ((lane >> 3) & 1) * 8 + (lane & 7)) * 128;
    }

    float o[8][4];
#pragma unroll
    for (int j = 0; j < 8; j++)
#pragma unroll
        for (int k = 0; k < 4; k++) o[j][k] = 0.f;
    float mrow[2] = {-1e30f, -1e30f};
    float lrow[2] = {0.f, 0.f};

    for (int t = 0; t < 32; t++) {
        __syncthreads();
        if (t + 1 < 32) issueKV(t + 1, (t + 1) & 1);
        CPCOMMIT();
        CPWAIT(1);
        __syncthreads();

        // ---- S = Q.K^T (log2 domain) ----
        float sc[8][4];
#pragma unroll
        for (int j = 0; j < 8; j++)
#pragma unroll
            for (int k = 0; k < 4; k++) sc[j][k] = 0.f;

#pragma unroll
        for (int kk = 0; kk < 4; kk++) {
#pragma unroll
            for (int ntp = 0; ntp < 4; ntp++) {
                uint32_t khf[4];
                ldsm4(khf, krow[ntp] + col[kk]);
                mma16816(sc[2*ntp],   qf[kk], khf[0], khf[2]);
                mma16816(sc[2*ntp+1], qf[kk], khf[1], khf[3]);
            }
        }

        // ---- online softmax (both h-chains interleaved, one ballot) ----
        {
            float tm0 = -1e30f, tm1 = -1e30f;
#pragma unroll
            for (int nt = 0; nt < 8; nt++) {
                tm0 = fmaxf(tm0, fmaxf(sc[nt][0], sc[nt][1]));
                tm1 = fmaxf(tm1, fmaxf(sc[nt][2], sc[nt][3]));
            }
            tm0 = fmaxf(tm0, __shfl_xor_sync(0xffffffffu, tm0, 1));
            tm1 = fmaxf(tm1, __shfl_xor_sync(0xffffffffu, tm1, 1));
            tm0 = fmaxf(tm0, __shfl_xor_sync(0xffffffffu, tm0, 2));
            tm1 = fmaxf(tm1, __shfl_xor_sync(0xffffffffu, tm1, 2));
            const float mo0 = mrow[0], mo1 = mrow[1];
            const float mn0 = fmaxf(mo0, tm0), mn1 = fmaxf(mo1, tm1);
            mrow[0] = mn0; mrow[1] = mn1;
            float rs0 = 0.f, rs1 = 0.f;
#pragma unroll
            for (int nt = 0; nt < 8; nt++) {
                const float p0 = exp2f(sc[nt][0] - mn0);
                const float p1 = exp2f(sc[nt][1] - mn0);
                const float p2 = exp2f(sc[nt][2] - mn1);
                const float p3 = exp2f(sc[nt][3] - mn1);
                sc[nt][0] = p0; sc[nt][1] = p1; sc[nt][2] = p2; sc[nt][3] = p3;
                rs0 += p0 + p1;
                rs1 += p2 + p3;
            }
            rs0 += __shfl_xor_sync(0xffffffffu, rs0, 1);
            rs1 += __shfl_xor_sync(0xffffffffu, rs1, 1);
            rs0 += __shfl_xor_sync(0xffffffffu, rs0, 2);
            rs1 += __shfl_xor_sync(0xffffffffu, rs1, 2);
            if (__ballot_sync(0xffffffffu, (mn0 != mo0) || (mn1 != mo1))) {
                const float c0 = exp2f(mo0 - mn0);
                const float c1 = exp2f(mo1 - mn1);
                lrow[0] = lrow[0] * c0 + rs0;
                lrow[1] = lrow[1] * c1 + rs1;
#pragma unroll
                for (int nt = 0; nt < 8; nt++) {
                    o[nt][0] *= c0; o[nt][1] *= c0;
                    o[nt][2] *= c1; o[nt][3] *= c1;
                }
            } else {
                lrow[0] += rs0;
                lrow[1] += rs1;
            }
        }

        // ---- O += P.V (P packed fp16 in registers) ----
#pragma unroll
        for (int kk = 0; kk < 4; kk++) {
            uint32_t pa[4];
            {
                const float* s0 = sc[2*kk];
                const float* s1 = sc[2*kk+1];
                pa[0] = pack_hf2(s0[1], s0[0]);
                pa[1] = pack_hf2(s0[3], s0[2]);
                pa[2] = pack_hf2(s1[1], s1[0]);
                pa[3] = pack_hf2(s1[3], s1[2]);
            }
#pragma unroll
            for (int ntp = 0; ntp < 4; ntp++) {
                uint32_t vhf[4];
                ldsm4t(vhf, vrow[kk] + col[ntp]);
                mma16816(o[2*ntp],   pa, vhf[0], vhf[1]);
                mma16816(o[2*ntp+1], pa, vhf[2], vhf[3]);
            }
        }

        // stage toggle
#pragma unroll
        for (int i = 0; i < 4; i++) {
            krow[i] ^= 0x4000u;
            vrow[i] ^= 0x8000u;
        }
    }

    // ---- epilogue: normalize, fp16, write straight into A buffer ----
    const int b = bh >> 4, head = bh & 15;
#pragma unroll
    for (int h = 0; h < 2; h++) {
        const float inv = 1.f / lrow[h];
        const int qr = q0 + 16 * w + 8 * h + (lane >> 2);
        const int m = b * L_ + qr;
        __half* rowp = Aout + (size_t)m * KA_ + head * HD_ + (lane & 3) * 2;
#pragma unroll
        for (int nt = 0; nt < 8; nt++) {
            const uint32_t hv = pack_hf2(o[nt][2*h+1] * inv, o[nt][2*h] * inv);
            *(uint32_t*)(rowp + 8 * nt) = hv;
        }
    }
}

// ============================================================================
// launch
// ============================================================================
extern "C" void kernel_launch(void* const* d_in, const int* in_sizes, int n_in,
                              void* d_out, int out_size)
{
    const float* query = (const float*)d_in[0];
    const float* key_  = (const float*)d_in[1];
    const float* value = (const float*)d_in[2];
    const float* Wq = (const float*)d_in[3];
    const float* bq = (const float*)d_in[4];
    const float* Wk = (const float*)d_in[5];
    const float* bk = (const float*)d_in[6];
    const float* Wv = (const float*)d_in[7];
    const float* bv = (const float*)d_in[8];
    const float* Wo = (const float*)d_in[9];
    const float* bo = (const float*)d_in[10];
    float* out = (float*)d_out;

    __half *Ab, *Wt, *QKV;
    cudaGetSymbolAddress((void**)&Ab,  g_A);
    cudaGetSymbolAddress((void**)&Wt,  g_Wt);
    cudaGetSymbolAddress((void**)&QKV, g_QKV);

    cudaFuncSetAttribute(gemm_proj, cudaFuncAttributeMaxDynamicSharedMemorySize, G_SMEM);
    cudaFuncSetAttribute(gemm_out,  cudaFuncAttributeMaxDynamicSharedMemorySize, G_SMEM);
    cudaFuncSetAttribute(attn_mma,  cudaFuncAttributeMaxDynamicSharedMemorySize, ATTN_SMEM);

    // 1. weight conversion (batched z=4)
    dim3 wg(32, 32, 4), wb(32, 8);
    split_weightT4<<<wg, wb>>>(Wq, Wk, Wv, Wo, Wt);

    // 2. input conversion (batched z=3)
    dim3 sg(MROWS * D_ / 1024, 3);
    split_rows3<<<sg, 256>>>(query, key_, value, Ab);

    // 3. q/k/v projections (batched z=3)
    dim3 gg(D_ / 128, MROWS / 256, 3);
    gemm_proj<<<gg, 512, G_SMEM>>>(Ab, Wt, bq, bk, bv, QKV);

    // 4. attention (writes fp16 A for the output GEMM directly)
    dim3 ag(L_ / 64, B_ * H_);    // (32, 32) = 1024 CTAs
    attn_mma<<<ag, 128, ATTN_SMEM>>>(QKV, QKV + (size_t)1 * HSZ,
                                     QKV + (size_t)2 * HSZ, Ab);

    // 5. output projection
    dim3 og(D_ / 128, MROWS / 256);
    gemm_out<<<og, 512, G_SMEM>>>(Ab, Wt + (size_t)3 * D_ * KA_, bo, out);
}

// round 8
// speedup vs baseline: 2.6351x; 1.0153x over previous
#include <cuda_runtime.h>
#include <cuda_fp16.h>
#include <cstdint>

#define B_  2
#define L_  2048
#define D_  1024
#define H_  16
#define HD_ 64
#define MROWS 4096
#define KA_ 1024
#define HSZ (B_ * H_ * L_ * HD_)

// Q pre-scale: 1/sqrt(64) * log2(e)  (softmax runs in log2 domain)
#define QSCALE 0.18033688011112042f

// ---------------- scratch (static device globals; no allocation allowed) ----
__device__ __half g_A[3][MROWS * KA_];      // fp16 activations; [0] reused for attn-out
__device__ __half g_Wt[4][D_ * KA_];        // transposed fp16 weights
__device__ __half g_QKV[3][HSZ];            // q/k/v fp16 [B,H,L,HD]

// ============================================================================
// helpers
// ============================================================================
__device__ __forceinline__ uint32_t smem_u32(const void* p) {
    uint32_t a;
    asm("{ .reg .u64 t; cvta.to.shared.u64 t, %1; cvt.u32.u64 %0, t; }" : "=r"(a) : "l"(p));
    return a;
}
__device__ __forceinline__ void cp16(uint32_t dst, const void* src) {
    asm volatile("cp.async.cg.shared.global [%0], [%1], 16;" :: "r"(dst), "l"(src));
}
#define CPCOMMIT() asm volatile("cp.async.commit_group;" ::: "memory")
#define CPWAIT(n)  asm volatile("cp.async.wait_group %0;" :: "n"(n) : "memory")

__device__ __forceinline__ void ldsm4(uint32_t r[4], uint32_t addr) {
    asm volatile("ldmatrix.sync.aligned.m8n8.x4.shared.b16 {%0,%1,%2,%3}, [%4];"
        : "=r"(r[0]), "=r"(r[1]), "=r"(r[2]), "=r"(r[3]) : "r"(addr));
}
__device__ __forceinline__ void ldsm4t(uint32_t r[4], uint32_t addr) {
    asm volatile("ldmatrix.sync.aligned.m8n8.x4.trans.shared.b16 {%0,%1,%2,%3}, [%4];"
        : "=r"(r[0]), "=r"(r[1]), "=r"(r[2]), "=r"(r[3]) : "r"(addr));
}
__device__ __forceinline__ void mma16816(float c[4], const uint32_t a[4],
                                         uint32_t b0, uint32_t b1) {
    asm volatile("mma.sync.aligned.m16n8k16.row.col.f32.f16.f16.f32 "
        "{%0,%1,%2,%3}, {%4,%5,%6,%7}, {%8,%9}, {%0,%1,%2,%3};"
        : "+f"(c[0]), "+f"(c[1]), "+f"(c[2]), "+f"(c[3])
        : "r"(a[0]), "r"(a[1]), "r"(a[2]), "r"(a[3]), "r"(b0), "r"(b1));
}
__device__ __forceinline__ uint32_t pack_hf2(float hiVal, float loVal) {
    uint32_t r;
    asm("cvt.rn.f16x2.f32 %0, %1, %2;" : "=r"(r) : "f"(hiVal), "f"(loVal));
    return r;
}
// single-MUFU exp2 (ex2.approx: ~2^-22 rel err, 1 instruction)
__device__ __forceinline__ float ex2(float x) {
    float y;
    asm("ex2.approx.ftz.f32 %0, %1;" : "=f"(y) : "f"(x));
    return y;
}

// ============================================================================
// batched conversions (single-term fp16)
// ============================================================================
__global__ void split_rows3(const float* __restrict__ X0, const float* __restrict__ X1,
                            const float* __restrict__ X2, __half* __restrict__ Abase)
{
    const int z = blockIdx.y;
    const float* X = (z == 0) ? X0 : (z == 1) ? X1 : X2;
    __half* A = Abase + (size_t)z * MROWS * KA_;
    const int idx = blockIdx.x * 256 + threadIdx.x;
    float4 v = *(const float4*)(X + (size_t)idx * 4);
    ushort4 hv;
    hv.x = __half_as_ushort(__float2half(v.x));
    hv.y = __half_as_ushort(__float2half(v.y));
    hv.z = __half_as_ushort(__float2half(v.z));
    hv.w = __half_as_ushort(__float2half(v.w));
    *(ushort4*)(A + (size_t)idx * 4) = hv;
}

__global__ void split_weightT4(const float* __restrict__ W0, const float* __restrict__ W1,
                               const float* __restrict__ W2, const float* __restrict__ W3,
                               __half* __restrict__ WtBase)
{
    __shared__ float t[32][33];
    const int z = blockIdx.z;
    const float* W = (z == 0) ? W0 : (z == 1) ? W1 : (z == 2) ? W2 : W3;
    __half* Wt = WtBase + (size_t)z * D_ * KA_;
    const int k0 = blockIdx.x * 32, n0 = blockIdx.y * 32;
    const int tx = threadIdx.x, ty = threadIdx.y;
    for (int i = ty; i < 32; i += 8)
        t[i][tx] = W[(size_t)(k0 + i) * D_ + n0 + tx];
    __syncthreads();
    for (int i = ty; i < 32; i += 8)
        Wt[(size_t)(n0 + i) * KA_ + k0 + tx] = __float2half(t[tx][i]);
}

// ============================================================================
// fp16 mma GEMM: C = A[M,1024] x Wt[N,1024]^T
// CTA 256x128, 512 threads, warp 64x32, 4-stage cp.async, 16 K-chunks of 64.
// ============================================================================
#define G_STAGE 49152
#define G_SMEM  (4 * G_STAGE)     // 196608

template <int MODE>   // 0: fp32 [M,D] out, 1: fp16 head-layout out
__device__ __forceinline__
void gemm_core(const __half* __restrict__ A, const __half* __restrict__ Bt,
               const float* __restrict__ bias, float* __restrict__ OutF,
               __half* __restrict__ OutH, float scale)
{
    extern __shared__ __align__(128) char smem[];
    const uint32_t sb = smem_u32(smem);
    const int tid = threadIdx.x, lane = tid & 31, warp = tid >> 5;
    const int wm = warp >> 2, wn = warp & 3;
    const int rowBase = blockIdx.y * 256;
    const int colBase = blockIdx.x * 128;

    float c[4][4][4];
#pragma unroll
    for (int i = 0; i < 4; i++)
#pragma unroll
        for (int j = 0; j < 4; j++)
#pragma unroll
            for (int k = 0; k < 4; k++) c[i][j][k] = 0.f;

    const int lr = tid >> 3, lg = tid & 7;

    auto issue = [&](int chunk, int s) {
        const uint32_t SA = sb + s * G_STAGE, SB = SA + 32768;
        const int c0 = chunk * 64;
#pragma unroll
        for (int j = 0; j < 4; j++) {
            const int r = 64 * j + lr;
            cp16(SA + r * 128 + ((lg ^ (r & 7)) << 4),
                 A + (size_t)(rowBase + r) * KA_ + c0 + lg * 8);
        }
#pragma unroll
        for (int j = 0; j < 2; j++) {
            const int r = 64 * j + lr;
            cp16(SB + r * 128 + ((lg ^ (r & 7)) << 4),
                 Bt + (size_t)(colBase + r) * KA_ + c0 + lg * 8);
        }
    };

    issue(0, 0); CPCOMMIT();
    issue(1, 1); CPCOMMIT();
    issue(2, 2); CPCOMMIT();

    for (int ch = 0; ch < 16; ch++) {
        __syncthreads();
        if (ch + 3 < 16) issue(ch + 3, (ch + 3) & 3);
        CPCOMMIT();
        CPWAIT(3);
        __syncthreads();

        const uint32_t SA = sb + (ch & 3) * G_STAGE, SB = SA + 32768;
#pragma unroll
        for (int kk = 0; kk < 4; kk++) {
            const int g = 2 * kk + (lane >> 4);
            uint32_t af[4][4];
#pragma unroll
            for (int mt = 0; mt < 4; mt++) {
                const int r = 64 * wm + 16 * mt + (lane & 15);
                ldsm4(af[mt], SA + r * 128 + ((g ^ (r & 7)) << 4));
            }
#pragma unroll
            for (int ntp = 0; ntp < 2; ntp++) {
                uint32_t bf[4];
                const int r = 32 * wn + 16 * ntp + (lane & 15);
                ldsm4(bf, SB + r * 128 + ((g ^ (r & 7)) << 4));
#pragma unroll
                for (int mt = 0; mt < 4; mt++) {
                    mma16816(c[mt][2*ntp],   af[mt], bf[0], bf[2]);
                    mma16816(c[mt][2*ntp+1], af[mt], bf[1], bf[3]);
                }
            }
        }
    }

#pragma unroll
    for (int mt = 0; mt < 4; mt++)
#pragma unroll
        for (int nt = 0; nt < 4; nt++) {
            const int n0 = colBase + 32 * wn + 8 * nt + (lane & 3) * 2;
            const float b0v = bias[n0], b1v = bias[n0 + 1];
#pragma unroll
            for (int h = 0; h < 2; h++) {
                const int m = rowBase + 64 * wm + 16 * mt + 8 * h + (lane >> 2);
                float v0 = c[mt][nt][2*h]   + b0v;
                float v1 = c[mt][nt][2*h+1] + b1v;
                if (MODE == 1) {
                    const uint32_t hi = pack_hf2(v1 * scale, v0 * scale);
                    const int bb = m >> 11, l = m & (L_ - 1);
                    const int hh = n0 >> 6, d = n0 & (HD_ - 1);
                    const size_t idx = ((size_t)(bb * H_ + hh) * L_ + l) * HD_ + d;
                    *(uint32_t*)((char*)OutH + idx * 2) = hi;
                } else {
                    float2 v = {v0, v1};
                    *(float2*)(OutF + (size_t)m * D_ + n0) = v;
                }
            }
        }
}

__global__ __launch_bounds__(512, 1)
void gemm_proj(const __half* __restrict__ Abase, const __half* __restrict__ WtBase,
               const float* __restrict__ bq, const float* __restrict__ bk,
               const float* __restrict__ bv, __half* __restrict__ QKV)
{
    const int z = blockIdx.z;
    const __half* A  = Abase  + (size_t)z * MROWS * KA_;
    const __half* Bt = WtBase + (size_t)z * D_ * KA_;
    const float* bias = (z == 0) ? bq : (z == 1) ? bk : bv;
    gemm_core<1>(A, Bt, bias, nullptr, QKV + (size_t)z * HSZ,
                 (z == 0) ? QSCALE : 1.0f);
}

__global__ __launch_bounds__(512, 1)
void gemm_out(const __half* __restrict__ A, const __half* __restrict__ Bt,
              const float* __restrict__ bias, float* __restrict__ Out)
{
    gemm_core<0>(A, Bt, bias, Out, nullptr, 1.0f);
}

// ============================================================================
// Flash attention fp16: CTA = 64 q-rows, 128 thr / 4 warps (warp = 16 rows).
// Separable-swizzle address precompute, XOR stage toggle, ex2.approx softmax.
// SMEM layout (offsets from sb): Q [0,0x2000); K0 [0x2000,0x4000);
// V0 [0x4000,0x6000); K1 [0x6000,0x8000); V1 [0xC000,0xE000). Total 56KB.
// K stage toggle = offset XOR 0x4000, V stage toggle = offset XOR 0x8000.
// ============================================================================
#define ATTN_SMEM 57344

__global__ __launch_bounds__(128, 4)
void attn_mma(const __half* __restrict__ Qg, const __half* __restrict__ Kg,
              const __half* __restrict__ Vg, __half* __restrict__ Aout)
{
    extern __shared__ __align__(128) char smem[];
    const uint32_t sb = smem_u32(smem);
    const int tid = threadIdx.x, lane = tid & 31, w = tid >> 5;
    const int q0 = blockIdx.x * 64;
    const int bh = blockIdx.y;
    const size_t base = (size_t)bh * L_ * HD_;

    const int lr = tid >> 3, lg = tid & 7;

    // Q tile -> [0, 0x2000)
#pragma unroll
    for (int j = 0; j < 4; j++) {
        const int r = 16 * j + lr;
        cp16(sb + r * 128 + ((lg ^ (r & 7)) << 4),
             Qg + base + (size_t)(q0 + r) * HD_ + lg * 8);
    }
    auto issueKV = [&](int t, int s) {
        const uint32_t kb = sb + (s ? 0x6000u : 0x2000u);
        const uint32_t vb = sb + (s ? 0xC000u : 0x4000u);
        const __half* ks = Kg + base + (size_t)(t * 64) * HD_;
        const __half* vs = Vg + base + (size_t)(t * 64) * HD_;
#pragma unroll
        for (int j = 0; j < 4; j++) {
            const int r = 16 * j + lr;
            const uint32_t off = r * 128 + ((lg ^ (r & 7)) << 4);
            cp16(kb + off, ks + (size_t)r * HD_ + lg * 8);
            cp16(vb + off, vs + (size_t)r * HD_ + lg * 8);
        }
    };
    issueKV(0, 0);
    CPCOMMIT();
    CPWAIT(0);
    __syncthreads();

    // separable swizzle pieces (all row indices = lane mod 8)
    uint32_t col[4];
#pragma unroll
    for (int i = 0; i < 4; i++)
        col[i] = sb + ((uint32_t)((2 * i + (lane >> 4)) ^ (lane & 7)) << 4);

    // hoisted Q fragments
    uint32_t qf[4][4];
#pragma unroll
    for (int kk = 0; kk < 4; kk++) {
        const uint32_t qrow = (uint32_t)(16 * w + (lane & 15)) * 128;
        ldsm4(qf[kk], col[kk] + qrow);
    }

    uint32_t krow[4], vrow[4];   // stage-resident row offsets (XOR-toggled)
#pragma unroll
    for (int i = 0; i < 4; i++) {
        krow[i] = 0x2000u + (uint32_t)(16 * i + (lane & 15)) * 128;
        vrow[i] = 0x4000u + (uint32_t)(16 * i + ((lane >> 3) & 1) * 8 + (lane & 7)) * 128;
    }

    float o[8][4];
#pragma unroll
    for (int j = 0; j < 8; j++)
#pragma unroll
        for (int k = 0; k < 4; k++) o[j][k] = 0.f;
    float mrow[2] = {-1e30f, -1e30f};
    float lrow[2] = {0.f, 0.f};

    for (int t = 0; t < 32; t++) {
        __syncthreads();
        if (t + 1 < 32) issueKV(t + 1, (t + 1) & 1);
        CPCOMMIT();
        CPWAIT(1);
        __syncthreads();

        // ---- S = Q.K^T (log2 domain) ----
        float sc[8][4];
#pragma unroll
        for (int j = 0; j < 8; j++)
#pragma unroll
            for (int k = 0; k < 4; k++) sc[j][k] = 0.f;

#pragma unroll
        for (int kk = 0; kk < 4; kk++) {
#pragma unroll
            for (int ntp = 0; ntp < 4; ntp++) {
                uint32_t khf[4];
                ldsm4(khf, krow[ntp] + col[kk]);
                mma16816(sc[2*ntp],   qf[kk], khf[0], khf[2]);
                mma16816(sc[2*ntp+1], qf[kk], khf[1], khf[3]);
            }
        }

        // ---- online softmax (ex2.approx, both h-chains, one ballot) ----
        {
            float tm0 = -1e30f, tm1 = -1e30f;
#pragma unroll
            for (int nt = 0; nt < 8; nt++) {
                tm0 = fmaxf(tm0, fmaxf(sc[nt][0], sc[nt][1]));
                tm1 = fmaxf(tm1, fmaxf(sc[nt][2], sc[nt][3]));
            }
            tm0 = fmaxf(tm0, __shfl_xor_sync(0xffffffffu, tm0, 1));
            tm1 = fmaxf(tm1, __shfl_xor_sync(0xffffffffu, tm1, 1));
            tm0 = fmaxf(tm0, __shfl_xor_sync(0xffffffffu, tm0, 2));
            tm1 = fmaxf(tm1, __shfl_xor_sync(0xffffffffu, tm1, 2));
            const float mo0 = mrow[0], mo1 = mrow[1];
            const float mn0 = fmaxf(mo0, tm0), mn1 = fmaxf(mo1, tm1);
            mrow[0] = mn0; mrow[1] = mn1;
            float rs0 = 0.f, rs1 = 0.f;
#pragma unroll
            for (int nt = 0; nt < 8; nt++) {
                const float p0 = ex2(sc[nt][0] - mn0);
                const float p1 = ex2(sc[nt][1] - mn0);
                const float p2 = ex2(sc[nt][2] - mn1);
                const float p3 = ex2(sc[nt][3] - mn1);
                sc[nt][0] = p0; sc[nt][1] = p1; sc[nt][2] = p2; sc[nt][3] = p3;
                rs0 += p0 + p1;
                rs1 += p2 + p3;
            }
            rs0 += __shfl_xor_sync(0xffffffffu, rs0, 1);
            rs1 += __shfl_xor_sync(0xffffffffu, rs1, 1);
            rs0 += __shfl_xor_sync(0xffffffffu, rs0, 2);
            rs1 += __shfl_xor_sync(0xffffffffu, rs1, 2);
            if (__ballot_sync(0xffffffffu, (mn0 != mo0) || (mn1 != mo1))) {
                const float c0 = ex2(mo0 - mn0);
                const float c1 = ex2(mo1 - mn1);
                lrow[0] = lrow[0] * c0 + rs0;
                lrow[1] = lrow[1] * c1 + rs1;
#pragma unroll
                for (int nt = 0; nt < 8; nt++) {
                    o[nt][0] *= c0; o[nt][1] *= c0;
                    o[nt][2] *= c1; o[nt][3] *= c1;
                }
            } else {
                lrow[0] += rs0;
                lrow[1] += rs1;
            }
        }

        // ---- O += P.V (P packed fp16 in registers) ----
#pragma unroll
        for (int kk = 0; kk < 4; kk++) {
            uint32_t pa[4];
            {
                const float* s0 = sc[2*kk];
                const float* s1 = sc[2*kk+1];
                pa[0] = pack_hf2(s0[1], s0[0]);
                pa[1] = pack_hf2(s0[3], s0[2]);
                pa[2] = pack_hf2(s1[1], s1[0]);
                pa[3] = pack_hf2(s1[3], s1[2]);
            }
#pragma unroll
            for (int ntp = 0; ntp < 4; ntp++) {
                uint32_t vhf[4];
                ldsm4t(vhf, vrow[kk] + col[ntp]);
                mma16816(o[2*ntp],   pa, vhf[0], vhf[1]);
                mma16816(o[2*ntp+1], pa, vhf[2], vhf[3]);
            }
        }

        // stage toggle
#pragma unroll
        for (int i = 0; i < 4; i++) {
            krow[i] ^= 0x4000u;
            vrow[i] ^= 0x8000u;
        }
    }

    // ---- epilogue: normalize, fp16, write straight into A buffer ----
    const int b = bh >> 4, head = bh & 15;
#pragma unroll
    for (int h = 0; h < 2; h++) {
        const float inv = 1.f / lrow[h];
        const int qr = q0 + 16 * w + 8 * h + (lane >> 2);
        const int m = b * L_ + qr;
        __half* rowp = Aout + (size_t)m * KA_ + head * HD_ + (lane & 3) * 2;
#pragma unroll
        for (int nt = 0; nt < 8; nt++) {
            const uint32_t hv = pack_hf2(o[nt][2*h+1] * inv, o[nt][2*h] * inv);
            *(uint32_t*)(rowp + 8 * nt) = hv;
        }
    }
}

// ============================================================================
// launch
// ============================================================================
extern "C" void kernel_launch(void* const* d_in, const int* in_sizes, int n_in,
                              void* d_out, int out_size)
{
    const float* query = (const float*)d_in[0];
    const float* key_  = (const float*)d_in[1];
    const float* value = (const float*)d_in[2];
    const float* Wq = (const float*)d_in[3];
    const float* bq = (const float*)d_in[4];
    const float* Wk = (const float*)d_in[5];
    const float* bk = (const float*)d_in[6];
    const float* Wv = (const float*)d_in[7];
    const float* bv = (const float*)d_in[8];
    const float* Wo = (const float*)d_in[9];
    const float* bo = (const float*)d_in[10];
    float* out = (float*)d_out;

    __half *Ab, *Wt, *QKV;
    cudaGetSymbolAddress((void**)&Ab,  g_A);
    cudaGetSymbolAddress((void**)&Wt,  g_Wt);
    cudaGetSymbolAddress((void**)&QKV, g_QKV);

    cudaFuncSetAttribute(gemm_proj, cudaFuncAttributeMaxDynamicSharedMemorySize, G_SMEM);
    cudaFuncSetAttribute(gemm_out,  cudaFuncAttributeMaxDynamicSharedMemorySize, G_SMEM);
    cudaFuncSetAttribute(attn_mma,  cudaFuncAttributeMaxDynamicSharedMemorySize, ATTN_SMEM);

    // 1. weight conversion (batched z=4)
    dim3 wg(32, 32, 4), wb(32, 8);
    split_weightT4<<<wg, wb>>>(Wq, Wk, Wv, Wo, Wt);

    // 2. input conversion (batched z=3)
    dim3 sg(MROWS * D_ / 1024, 3);
    split_rows3<<<sg, 256>>>(query, key_, value, Ab);

    // 3. q/k/v projections (batched z=3)
    dim3 gg(D_ / 128, MROWS / 256, 3);
    gemm_proj<<<gg, 512, G_SMEM>>>(Ab, Wt, bq, bk, bv, QKV);

    // 4. attention (writes fp16 A for the output GEMM directly)
    dim3 ag(L_ / 64, B_ * H_);    // (32, 32) = 1024 CTAs
    attn_mma<<<ag, 128, ATTN_SMEM>>>(QKV, QKV + (size_t)1 * HSZ,
                                     QKV + (size_t)2 * HSZ, Ab);

    // 5. output projection
    dim3 og(D_ / 128, MROWS / 256);
    gemm_out<<<og, 512, G_SMEM>>>(Ab, Wt + (size_t)3 * D_ * KA_, bo, out);
}

// round 9
// speedup vs baseline: 2.6406x; 1.0021x over previous
#include <cuda_runtime.h>
#include <cuda_fp16.h>
#include <cstdint>

#define B_  2
#define L_  2048
#define D_  1024
#define H_  16
#define HD_ 64
#define MROWS 4096
#define KA_ 1024
#define HSZ (B_ * H_ * L_ * HD_)

// Q pre-scale: 1/sqrt(64) * log2(e)  (softmax runs in log2 domain)
#define QSCALE 0.18033688011112042f
#define ONES_H2 0x3C003C00u      // fp16x2 {1.0, 1.0}

// ---------------- scratch (static device globals; no allocation allowed) ----
__device__ __half g_A[3][MROWS * KA_];      // fp16 activations; [0] reused for attn-out
__device__ __half g_Wt[4][D_ * KA_];        // transposed fp16 weights
__device__ __half g_QKV[3][HSZ];            // q/k/v fp16 [B,H,L,HD]

// ============================================================================
// helpers
// ============================================================================
__device__ __forceinline__ uint32_t smem_u32(const void* p) {
    uint32_t a;
    asm("{ .reg .u64 t; cvta.to.shared.u64 t, %1; cvt.u32.u64 %0, t; }" : "=r"(a) : "l"(p));
    return a;
}
__device__ __forceinline__ void cp16(uint32_t dst, const void* src) {
    asm volatile("cp.async.cg.shared.global [%0], [%1], 16;" :: "r"(dst), "l"(src));
}
#define CPCOMMIT() asm volatile("cp.async.commit_group;" ::: "memory")
#define CPWAIT(n)  asm volatile("cp.async.wait_group %0;" :: "n"(n) : "memory")

__device__ __forceinline__ void ldsm4(uint32_t r[4], uint32_t addr) {
    asm volatile("ldmatrix.sync.aligned.m8n8.x4.shared.b16 {%0,%1,%2,%3}, [%4];"
        : "=r"(r[0]), "=r"(r[1]), "=r"(r[2]), "=r"(r[3]) : "r"(addr));
}
__device__ __forceinline__ void ldsm4t(uint32_t r[4], uint32_t addr) {
    asm volatile("ldmatrix.sync.aligned.m8n8.x4.trans.shared.b16 {%0,%1,%2,%3}, [%4];"
        : "=r"(r[0]), "=r"(r[1]), "=r"(r[2]), "=r"(r[3]) : "r"(addr));
}
__device__ __forceinline__ void mma16816(float c[4], const uint32_t a[4],
                                         uint32_t b0, uint32_t b1) {
    asm volatile("mma.sync.aligned.m16n8k16.row.col.f32.f16.f16.f32 "
        "{%0,%1,%2,%3}, {%4,%5,%6,%7}, {%8,%9}, {%0,%1,%2,%3};"
        : "+f"(c[0]), "+f"(c[1]), "+f"(c[2]), "+f"(c[3])
        : "r"(a[0]), "r"(a[1]), "r"(a[2]), "r"(a[3]), "r"(b0), "r"(b1));
}
__device__ __forceinline__ uint32_t pack_hf2(float hiVal, float loVal) {
    uint32_t r;
    asm("cvt.rn.f16x2.f32 %0, %1, %2;" : "=r"(r) : "f"(hiVal), "f"(loVal));
    return r;
}
// fp32 single-MUFU exp2
__device__ __forceinline__ float ex2(float x) {
    float y;
    asm("ex2.approx.ftz.f32 %0, %1;" : "=f"(y) : "f"(x));
    return y;
}
// packed fp16x2 exp2 — one MUFU for two values
__device__ __forceinline__ uint32_t ex2h2(uint32_t x) {
    uint32_t y;
    asm("ex2.approx.f16x2 %0, %1;" : "=r"(y) : "r"(x));
    return y;
}

// ============================================================================
// batched conversions (single-term fp16)
// ============================================================================
__global__ void split_rows3(const float* __restrict__ X0, const float* __restrict__ X1,
                            const float* __restrict__ X2, __half* __restrict__ Abase)
{
    const int z = blockIdx.y;
    const float* X = (z == 0) ? X0 : (z == 1) ? X1 : X2;
    __half* A = Abase + (size_t)z * MROWS * KA_;
    const int idx = blockIdx.x * 256 + threadIdx.x;
    float4 v = *(const float4*)(X + (size_t)idx * 4);
    ushort4 hv;
    hv.x = __half_as_ushort(__float2half(v.x));
    hv.y = __half_as_ushort(__float2half(v.y));
    hv.z = __half_as_ushort(__float2half(v.z));
    hv.w = __half_as_ushort(__float2half(v.w));
    *(ushort4*)(A + (size_t)idx * 4) = hv;
}

__global__ void split_weightT4(const float* __restrict__ W0, const float* __restrict__ W1,
                               const float* __restrict__ W2, const float* __restrict__ W3,
                               __half* __restrict__ WtBase)
{
    __shared__ float t[32][33];
    const int z = blockIdx.z;
    const float* W = (z == 0) ? W0 : (z == 1) ? W1 : (z == 2) ? W2 : W3;
    __half* Wt = WtBase + (size_t)z * D_ * KA_;
    const int k0 = blockIdx.x * 32, n0 = blockIdx.y * 32;
    const int tx = threadIdx.x, ty = threadIdx.y;
    for (int i = ty; i < 32; i += 8)
        t[i][tx] = W[(size_t)(k0 + i) * D_ + n0 + tx];
    __syncthreads();
    for (int i = ty; i < 32; i += 8)
        Wt[(size_t)(n0 + i) * KA_ + k0 + tx] = __float2half(t[tx][i]);
}

// ============================================================================
// fp16 mma GEMM: C = A[M,1024] x Wt[N,1024]^T
// CTA 256x128, 512 threads, warp 64x32, 4-stage cp.async, 16 K-chunks of 64.
// ============================================================================
#define G_STAGE 49152
#define G_SMEM  (4 * G_STAGE)     // 196608

template <int MODE>   // 0: fp32 [M,D] out, 1: fp16 head-layout out
__device__ __forceinline__
void gemm_core(const __half* __restrict__ A, const __half* __restrict__ Bt,
               const float* __restrict__ bias, float* __restrict__ OutF,
               __half* __restrict__ OutH, float scale)
{
    extern __shared__ __align__(128) char smem[];
    const uint32_t sb = smem_u32(smem);
    const int tid = threadIdx.x, lane = tid & 31, warp = tid >> 5;
    const int wm = warp >> 2, wn = warp & 3;
    const int rowBase = blockIdx.y * 256;
    const int colBase = blockIdx.x * 128;

    float c[4][4][4];
#pragma unroll
    for (int i = 0; i < 4; i++)
#pragma unroll
        for (int j = 0; j < 4; j++)
#pragma unroll
            for (int k = 0; k < 4; k++) c[i][j][k] = 0.f;

    const int lr = tid >> 3, lg = tid & 7;

    auto issue = [&](int chunk, int s) {
        const uint32_t SA = sb + s * G_STAGE, SB = SA + 32768;
        const int c0 = chunk * 64;
#pragma unroll
        for (int j = 0; j < 4; j++) {
            const int r = 64 * j + lr;
            cp16(SA + r * 128 + ((lg ^ (r & 7)) << 4),
                 A + (size_t)(rowBase + r) * KA_ + c0 + lg * 8);
        }
#pragma unroll
        for (int j = 0; j < 2; j++) {
            const int r = 64 * j + lr;
            cp16(SB + r * 128 + ((lg ^ (r & 7)) << 4),
                 Bt + (size_t)(colBase + r) * KA_ + c0 + lg * 8);
        }
    };

    issue(0, 0); CPCOMMIT();
    issue(1, 1); CPCOMMIT();
    issue(2, 2); CPCOMMIT();

    for (int ch = 0; ch < 16; ch++) {
        __syncthreads();
        if (ch + 3 < 16) issue(ch + 3, (ch + 3) & 3);
        CPCOMMIT();
        CPWAIT(3);
        __syncthreads();

        const uint32_t SA = sb + (ch & 3) * G_STAGE, SB = SA + 32768;
#pragma unroll
        for (int kk = 0; kk < 4; kk++) {
            const int g = 2 * kk + (lane >> 4);
            uint32_t af[4][4];
#pragma unroll
            for (int mt = 0; mt < 4; mt++) {
                const int r = 64 * wm + 16 * mt + (lane & 15);
                ldsm4(af[mt], SA + r * 128 + ((g ^ (r & 7)) << 4));
            }
#pragma unroll
            for (int ntp = 0; ntp < 2; ntp++) {
                uint32_t bf[4];
                const int r = 32 * wn + 16 * ntp + (lane & 15);
                ldsm4(bf, SB + r * 128 + ((g ^ (r & 7)) << 4));
#pragma unroll
                for (int mt = 0; mt < 4; mt++) {
                    mma16816(c[mt][2*ntp],   af[mt], bf[0], bf[2]);
                    mma16816(c[mt][2*ntp+1], af[mt], bf[1], bf[3]);
                }
            }
        }
    }

#pragma unroll
    for (int mt = 0; mt < 4; mt++)
#pragma unroll
        for (int nt = 0; nt < 4; nt++) {
            const int n0 = colBase + 32 * wn + 8 * nt + (lane & 3) * 2;
            const float b0v = bias[n0], b1v = bias[n0 + 1];
#pragma unroll
            for (int h = 0; h < 2; h++) {
                const int m = rowBase + 64 * wm + 16 * mt + 8 * h + (lane >> 2);
                float v0 = c[mt][nt][2*h]   + b0v;
                float v1 = c[mt][nt][2*h+1] + b1v;
                if (MODE == 1) {
                    const uint32_t hi = pack_hf2(v1 * scale, v0 * scale);
                    const int bb = m >> 11, l = m & (L_ - 1);
                    const int hh = n0 >> 6, d = n0 & (HD_ - 1);
                    const size_t idx = ((size_t)(bb * H_ + hh) * L_ + l) * HD_ + d;
                    *(uint32_t*)((char*)OutH + idx * 2) = hi;
                } else {
                    float2 v = {v0, v1};
                    *(float2*)(OutF + (size_t)m * D_ + n0) = v;
                }
            }
        }
}

__global__ __launch_bounds__(512, 1)
void gemm_proj(const __half* __restrict__ Abase, const __half* __restrict__ WtBase,
               const float* __restrict__ bq, const float* __restrict__ bk,
               const float* __restrict__ bv, __half* __restrict__ QKV)
{
    const int z = blockIdx.z;
    const __half* A  = Abase  + (size_t)z * MROWS * KA_;
    const __half* Bt = WtBase + (size_t)z * D_ * KA_;
    const float* bias = (z == 0) ? bq : (z == 1) ? bk : bv;
    gemm_core<1>(A, Bt, bias, nullptr, QKV + (size_t)z * HSZ,
                 (z == 0) ? QSCALE : 1.0f);
}

__global__ __launch_bounds__(512, 1)
void gemm_out(const __half* __restrict__ A, const __half* __restrict__ Bt,
              const float* __restrict__ bias, float* __restrict__ Out)
{
    gemm_core<0>(A, Bt, bias, Out, nullptr, 1.0f);
}

// ============================================================================
// Flash attention fp16: CTA = 64 q-rows, 128 thr / 4 warps (warp = 16 rows).
// Softmax: fp32 max + fp32 subtract, fp16x2 packed ex2 (16 MUFU/tile),
// row-sum l = P*ones via 4 extra HMMA (no FADD/shfl chain).
// SMEM: Q [0,0x2000); K0 [0x2000); V0 [0x4000); K1 [0x6000); V1 [0xC000).
// K stage toggle = XOR 0x4000, V stage toggle = XOR 0x8000. Total 56KB.
// ============================================================================
#define ATTN_SMEM 57344

__global__ __launch_bounds__(128, 4)
void attn_mma(const __half* __restrict__ Qg, const __half* __restrict__ Kg,
              const __half* __restrict__ Vg, __half* __restrict__ Aout)
{
    extern __shared__ __align__(128) char smem[];
    const uint32_t sb = smem_u32(smem);
    const int tid = threadIdx.x, lane = tid & 31, w = tid >> 5;
    const int q0 = blockIdx.x * 64;
    const int bh = blockIdx.y;
    const size_t base = (size_t)bh * L_ * HD_;

    const int lr = tid >> 3, lg = tid & 7;

    // Q tile -> [0, 0x2000)
#pragma unroll
    for (int j = 0; j < 4; j++) {
        const int r = 16 * j + lr;
        cp16(sb + r * 128 + ((lg ^ (r & 7)) << 4),
             Qg + base + (size_t)(q0 + r) * HD_ + lg * 8);
    }
    auto issueKV = [&](int t, int s) {
        const uint32_t kb = sb + (s ? 0x6000u : 0x2000u);
        const uint32_t vb = sb + (s ? 0xC000u : 0x4000u);
        const __half* ks = Kg + base + (size_t)(t * 64) * HD_;
        const __half* vs = Vg + base + (size_t)(t * 64) * HD_;
#pragma unroll
        for (int j = 0; j < 4; j++) {
            const int r = 16 * j + lr;
            const uint32_t off = r * 128 + ((lg ^ (r & 7)) << 4);
            cp16(kb + off, ks + (size_t)r * HD_ + lg * 8);
            cp16(vb + off, vs + (size_t)r * HD_ + lg * 8);
        }
    };
    issueKV(0, 0);
    CPCOMMIT();
    CPWAIT(0);
    __syncthreads();

    // separable swizzle pieces (all row indices = lane mod 8)
    uint32_t col[4];
#pragma unroll
    for (int i = 0; i < 4; i++)
        col[i] = sb + ((uint32_t)((2 * i + (lane >> 4)) ^ (lane & 7)) << 4);

    // hoisted Q fragments
    uint32_t qf[4][4];
#pragma unroll
    for (int kk = 0; kk < 4; kk++) {
        const uint32_t qrow = (uint32_t)(16 * w + (lane & 15)) * 128;
        ldsm4(qf[kk], col[kk] + qrow);
    }

    uint32_t krow[4], vrow[4];   // stage-resident row offsets (XOR-toggled)
#pragma unroll
    for (int i = 0; i < 4; i++) {
        krow[i] = 0x2000u + (uint32_t)(16 * i + (lane & 15)) * 128;
        vrow[i] = 0x4000u + (uint32_t)(16 * i + ((lane >> 3) & 1) * 8 + (lane & 7)) * 128;
    }

    float o[8][4];
#pragma unroll
    for (int j = 0; j < 8; j++)
#pragma unroll
        for (int k = 0; k < 4; k++) o[j][k] = 0.f;
    float mrow[2] = {-1e30f, -1e30f};
    float lrow[2] = {0.f, 0.f};

    for (int t = 0; t < 32; t++) {
        __syncthreads();
        if (t + 1 < 32) issueKV(t + 1, (t + 1) & 1);
        CPCOMMIT();
        CPWAIT(1);
        __syncthreads();

        // ---- S = Q.K^T (log2 domain) ----
        float sc[8][4];
#pragma unroll
        for (int j = 0; j < 8; j++)
#pragma unroll
            for (int k = 0; k < 4; k++) sc[j][k] = 0.f;

#pragma unroll
        for (int kk = 0; kk < 4; kk++) {
#pragma unroll
            for (int ntp = 0; ntp < 4; ntp++) {
                uint32_t khf[4];
                ldsm4(khf, krow[ntp] + col[kk]);
                mma16816(sc[2*ntp],   qf[kk], khf[0], khf[2]);
                mma16816(sc[2*ntp+1], qf[kk], khf[1], khf[3]);
            }
        }

        // ---- softmax: max (fp32) -> subtract (fp32) -> packed fp16x2 ex2 ----
        uint32_t p0[8], p1[8];    // packed P fragments: h0 rows / h1 rows
        {
            float tm0 = -1e30f, tm1 = -1e30f;
#pragma unroll
            for (int nt = 0; nt < 8; nt++) {
                tm0 = fmaxf(tm0, fmaxf(sc[nt][0], sc[nt][1]));
                tm1 = fmaxf(tm1, fmaxf(sc[nt][2], sc[nt][3]));
            }
            tm0 = fmaxf(tm0, __shfl_xor_sync(0xffffffffu, tm0, 1));
            tm1 = fmaxf(tm1, __shfl_xor_sync(0xffffffffu, tm1, 1));
            tm0 = fmaxf(tm0, __shfl_xor_sync(0xffffffffu, tm0, 2));
            tm1 = fmaxf(tm1, __shfl_xor_sync(0xffffffffu, tm1, 2));
            const float mo0 = mrow[0], mo1 = mrow[1];
            const float mn0 = fmaxf(mo0, tm0), mn1 = fmaxf(mo1, tm1);
            mrow[0] = mn0; mrow[1] = mn1;
#pragma unroll
            for (int nt = 0; nt < 8; nt++) {
                p0[nt] = ex2h2(pack_hf2(sc[nt][1] - mn0, sc[nt][0] - mn0));
                p1[nt] = ex2h2(pack_hf2(sc[nt][3] - mn1, sc[nt][2] - mn1));
            }
            // o-rescale (before PV accumulates); lrow scaled now, += lacc later
            if (__ballot_sync(0xffffffffu, (mn0 != mo0) || (mn1 != mo1))) {
                const float c0 = ex2(mo0 - mn0);
                const float c1 = ex2(mo1 - mn1);
                lrow[0] *= c0;
                lrow[1] *= c1;
#pragma unroll
                for (int nt = 0; nt < 8; nt++) {
                    o[nt][0] *= c0; o[nt][1] *= c0;
                    o[nt][2] *= c1; o[nt][3] *= c1;
                }
            }
        }

        // ---- l = P . ones (tensor core row-sum) + O += P . V ----
        float lacc[4] = {0.f, 0.f, 0.f, 0.f};
#pragma unroll
        for (int kk = 0; kk < 4; kk++) {
            const uint32_t pa[4] = {p0[2*kk], p1[2*kk], p0[2*kk+1], p1[2*kk+1]};
            mma16816(lacc, pa, ONES_H2, ONES_H2);
#pragma unroll
            for (int ntp = 0; ntp < 4; ntp++) {
                uint32_t vhf[4];
                ldsm4t(vhf, vrow[kk] + col[ntp]);
                mma16816(o[2*ntp],   pa, vhf[0], vhf[1]);
                mma16816(o[2*ntp+1], pa, vhf[2], vhf[3]);
            }
        }
        lrow[0] += lacc[0];
        lrow[1] += lacc[2];

        // stage toggle
#pragma unroll
        for (int i = 0; i < 4; i++) {
            krow[i] ^= 0x4000u;
            vrow[i] ^= 0x8000u;
        }
    }

    // ---- epilogue: normalize, fp16, write straight into A buffer ----
    const int b = bh >> 4, head = bh & 15;
#pragma unroll
    for (int h = 0; h < 2; h++) {
        const float inv = 1.f / lrow[h];
        const int qr = q0 + 16 * w + 8 * h + (lane >> 2);
        const int m = b * L_ + qr;
        __half* rowp = Aout + (size_t)m * KA_ + head * HD_ + (lane & 3) * 2;
#pragma unroll
        for (int nt = 0; nt < 8; nt++) {
            const uint32_t hv = pack_hf2(o[nt][2*h+1] * inv, o[nt][2*h] * inv);
            *(uint32_t*)(rowp + 8 * nt) = hv;
        }
    }
}

// ============================================================================
// launch
// ============================================================================
extern "C" void kernel_launch(void* const* d_in, const int* in_sizes, int n_in,
                              void* d_out, int out_size)
{
    const float* query = (const float*)d_in[0];
    const float* key_  = (const float*)d_in[1];
    const float* value = (const float*)d_in[2];
    const float* Wq = (const float*)d_in[3];
    const float* bq = (const float*)d_in[4];
    const float* Wk = (const float*)d_in[5];
    const float* bk = (const float*)d_in[6];
    const float* Wv = (const float*)d_in[7];
    const float* bv = (const float*)d_in[8];
    const float* Wo = (const float*)d_in[9];
    const float* bo = (const float*)d_in[10];
    float* out = (float*)d_out;

    __half *Ab, *Wt, *QKV;
    cudaGetSymbolAddress((void**)&Ab,  g_A);
    cudaGetSymbolAddress((void**)&Wt,  g_Wt);
    cudaGetSymbolAddress((void**)&QKV, g_QKV);

    cudaFuncSetAttribute(gemm_proj, cudaFuncAttributeMaxDynamicSharedMemorySize, G_SMEM);
    cudaFuncSetAttribute(gemm_out,  cudaFuncAttributeMaxDynamicSharedMemorySize, G_SMEM);
    cudaFuncSetAttribute(attn_mma,  cudaFuncAttributeMaxDynamicSharedMemorySize, ATTN_SMEM);

    // 1. weight conversion (batched z=4)
    dim3 wg(32, 32, 4), wb(32, 8);
    split_weightT4<<<wg, wb>>>(Wq, Wk, Wv, Wo, Wt);

    // 2. input conversion (batched z=3)
    dim3 sg(MROWS * D_ / 1024, 3);
    split_rows3<<<sg, 256>>>(query, key_, value, Ab);

    // 3. q/k/v projections (batched z=3)
    dim3 gg(D_ / 128, MROWS / 256, 3);
    gemm_proj<<<gg, 512, G_SMEM>>>(Ab, Wt, bq, bk, bv, QKV);

    // 4. attention (writes fp16 A for the output GEMM directly)
    dim3 ag(L_ / 64, B_ * H_);    // (32, 32) = 1024 CTAs
    attn_mma<<<ag, 128, ATTN_SMEM>>>(QKV, QKV + (size_t)1 * HSZ,
                                     QKV + (size_t)2 * HSZ, Ab);

    // 5. output projection
    dim3 og(D_ / 128, MROWS / 256);
    gemm_out<<<og, 512, G_SMEM>>>(Ab, Wt + (size_t)3 * D_ * KA_, bo, out);
}

// round 10
// speedup vs baseline: 2.6569x; 1.0062x over previous
#include <cuda_runtime.h>
#include <cuda_fp16.h>
#include <cstdint>

#define B_  2
#define L_  2048
#define D_  1024
#define H_  16
#define HD_ 64
#define MROWS 4096
#define KA_ 1024
#define HSZ (B_ * H_ * L_ * HD_)

// Q pre-scale: 1/sqrt(64) * log2(e)  (softmax runs in log2 domain)
#define QSCALE 0.18033688011112042f

// ---------------- scratch (static device globals; no allocation allowed) ----
__device__ __half g_A[3][MROWS * KA_];      // fp16 activations; [0] reused for attn-out
__device__ __half g_Wt[4][D_ * KA_];        // transposed fp16 weights
__device__ __half g_QKV[3][HSZ];            // q/k/v fp16 [B,H,L,HD]

// ============================================================================
// helpers
// ============================================================================
__device__ __forceinline__ uint32_t smem_u32(const void* p) {
    uint32_t a;
    asm("{ .reg .u64 t; cvta.to.shared.u64 t, %1; cvt.u32.u64 %0, t; }" : "=r"(a) : "l"(p));
    return a;
}
__device__ __forceinline__ void cp16(uint32_t dst, const void* src) {
    asm volatile("cp.async.cg.shared.global [%0], [%1], 16;" :: "r"(dst), "l"(src));
}
#define CPCOMMIT() asm volatile("cp.async.commit_group;" ::: "memory")
#define CPWAIT(n)  asm volatile("cp.async.wait_group %0;" :: "n"(n) : "memory")

__device__ __forceinline__ void ldsm4(uint32_t r[4], uint32_t addr) {
    asm volatile("ldmatrix.sync.aligned.m8n8.x4.shared.b16 {%0,%1,%2,%3}, [%4];"
        : "=r"(r[0]), "=r"(r[1]), "=r"(r[2]), "=r"(r[3]) : "r"(addr));
}
__device__ __forceinline__ void ldsm4t(uint32_t r[4], uint32_t addr) {
    asm volatile("ldmatrix.sync.aligned.m8n8.x4.trans.shared.b16 {%0,%1,%2,%3}, [%4];"
        : "=r"(r[0]), "=r"(r[1]), "=r"(r[2]), "=r"(r[3]) : "r"(addr));
}
__device__ __forceinline__ void mma16816(float c[4], const uint32_t a[4],
                                         uint32_t b0, uint32_t b1) {
    asm volatile("mma.sync.aligned.m16n8k16.row.col.f32.f16.f16.f32 "
        "{%0,%1,%2,%3}, {%4,%5,%6,%7}, {%8,%9}, {%0,%1,%2,%3};"
        : "+f"(c[0]), "+f"(c[1]), "+f"(c[2]), "+f"(c[3])
        : "r"(a[0]), "r"(a[1]), "r"(a[2]), "r"(a[3]), "r"(b0), "r"(b1));
}
__device__ __forceinline__ uint32_t pack_hf2(float hiVal, float loVal) {
    uint32_t r;
    asm("cvt.rn.f16x2.f32 %0, %1, %2;" : "=r"(r) : "f"(hiVal), "f"(loVal));
    return r;
}
// fp32 single-MUFU exp2
__device__ __forceinline__ float ex2(float x) {
    float y;
    asm("ex2.approx.ftz.f32 %0, %1;" : "=f"(y) : "f"(x));
    return y;
}

// ============================================================================
// batched conversions (single-term fp16)
// ============================================================================
__global__ void split_rows3(const float* __restrict__ X0, const float* __restrict__ X1,
                            const float* __restrict__ X2, __half* __restrict__ Abase)
{
    const int z = blockIdx.y;
    const float* X = (z == 0) ? X0 : (z == 1) ? X1 : X2;
    __half* A = Abase + (size_t)z * MROWS * KA_;
    const int idx = blockIdx.x * 256 + threadIdx.x;
    float4 v = *(const float4*)(X + (size_t)idx * 4);
    ushort4 hv;
    hv.x = __half_as_ushort(__float2half(v.x));
    hv.y = __half_as_ushort(__float2half(v.y));
    hv.z = __half_as_ushort(__float2half(v.z));
    hv.w = __half_as_ushort(__float2half(v.w));
    *(ushort4*)(A + (size_t)idx * 4) = hv;
}

__global__ void split_weightT4(const float* __restrict__ W0, const float* __restrict__ W1,
                               const float* __restrict__ W2, const float* __restrict__ W3,
                               __half* __restrict__ WtBase)
{
    __shared__ float t[32][33];
    const int z = blockIdx.z;
    const float* W = (z == 0) ? W0 : (z == 1) ? W1 : (z == 2) ? W2 : W3;
    __half* Wt = WtBase + (size_t)z * D_ * KA_;
    const int k0 = blockIdx.x * 32, n0 = blockIdx.y * 32;
    const int tx = threadIdx.x, ty = threadIdx.y;
    for (int i = ty; i < 32; i += 8)
        t[i][tx] = W[(size_t)(k0 + i) * D_ + n0 + tx];
    __syncthreads();
    for (int i = ty; i < 32; i += 8)
        Wt[(size_t)(n0 + i) * KA_ + k0 + tx] = __float2half(t[tx][i]);
}

// ============================================================================
// fp16 mma GEMM: C = A[M,1024] x Wt[N,1024]^T
// CTA 256x128, 512 threads, warp 64x32, 4-stage cp.async, 16 K-chunks of 64.
// Single __syncthreads per chunk: issue into stage (ch+3)&3 goes AFTER the
// barrier that ends chunk ch-1 (same stage, readers provably done).
// ============================================================================
#define G_STAGE 49152
#define G_SMEM  (4 * G_STAGE)     // 196608

template <int MODE>   // 0: fp32 [M,D] out, 1: fp16 head-layout out
__device__ __forceinline__
void gemm_core(const __half* __restrict__ A, const __half* __restrict__ Bt,
               const float* __restrict__ bias, float* __restrict__ OutF,
               __half* __restrict__ OutH, float scale)
{
    extern __shared__ __align__(128) char smem[];
    const uint32_t sb = smem_u32(smem);
    const int tid = threadIdx.x, lane = tid & 31, warp = tid >> 5;
    const int wm = warp >> 2, wn = warp & 3;
    const int rowBase = blockIdx.y * 256;
    const int colBase = blockIdx.x * 128;

    float c[4][4][4];
#pragma unroll
    for (int i = 0; i < 4; i++)
#pragma unroll
        for (int j = 0; j < 4; j++)
#pragma unroll
            for (int k = 0; k < 4; k++) c[i][j][k] = 0.f;

    const int lr = tid >> 3, lg = tid & 7;

    auto issue = [&](int chunk, int s) {
        const uint32_t SA = sb + s * G_STAGE, SB = SA + 32768;
        const int c0 = chunk * 64;
#pragma unroll
        for (int j = 0; j < 4; j++) {
            const int r = 64 * j + lr;
            cp16(SA + r * 128 + ((lg ^ (r & 7)) << 4),
                 A + (size_t)(rowBase + r) * KA_ + c0 + lg * 8);
        }
#pragma unroll
        for (int j = 0; j < 2; j++) {
            const int r = 64 * j + lr;
            cp16(SB + r * 128 + ((lg ^ (r & 7)) << 4),
                 Bt + (size_t)(colBase + r) * KA_ + c0 + lg * 8);
        }
    };

    issue(0, 0); CPCOMMIT();
    issue(1, 1); CPCOMMIT();
    issue(2, 2); CPCOMMIT();
    CPWAIT(2);                 // chunk 0 resident (this thread)
    __syncthreads();           // visible CTA-wide

    for (int ch = 0; ch < 16; ch++) {
        if (ch + 3 < 16) issue(ch + 3, (ch + 3) & 3);   // stage freed by ch-1
        CPCOMMIT();

        const uint32_t SA = sb + (ch & 3) * G_STAGE, SB = SA + 32768;
#pragma unroll
        for (int kk = 0; kk < 4; kk++) {
            const int g = 2 * kk + (lane >> 4);
            uint32_t af[4][4];
#pragma unroll
            for (int mt = 0; mt < 4; mt++) {
                const int r = 64 * wm + 16 * mt + (lane & 15);
                ldsm4(af[mt], SA + r * 128 + ((g ^ (r & 7)) << 4));
            }
#pragma unroll
            for (int ntp = 0; ntp < 2; ntp++) {
                uint32_t bf[4];
                const int r = 32 * wn + 16 * ntp + (lane & 15);
                ldsm4(bf, SB + r * 128 + ((g ^ (r & 7)) << 4));
#pragma unroll
                for (int mt = 0; mt < 4; mt++) {
                    mma16816(c[mt][2*ntp],   af[mt], bf[0], bf[2]);
                    mma16816(c[mt][2*ntp+1], af[mt], bf[1], bf[3]);
                }
            }
        }

        if (ch < 15) {
            CPWAIT(2);         // chunk ch+1 resident
            __syncthreads();   // visibility + WAR fence for next issue
        }
    }

#pragma unroll
    for (int mt = 0; mt < 4; mt++)
#pragma unroll
        for (int nt = 0; nt < 4; nt++) {
            const int n0 = colBase + 32 * wn + 8 * nt + (lane & 3) * 2;
            const float b0v = bias[n0], b1v = bias[n0 + 1];
#pragma unroll
            for (int h = 0; h < 2; h++) {
                const int m = rowBase + 64 * wm + 16 * mt + 8 * h + (lane >> 2);
                float v0 = c[mt][nt][2*h]   + b0v;
                float v1 = c[mt][nt][2*h+1] + b1v;
                if (MODE == 1) {
                    const uint32_t hi = pack_hf2(v1 * scale, v0 * scale);
                    const int bb = m >> 11, l = m & (L_ - 1);
                    const int hh = n0 >> 6, d = n0 & (HD_ - 1);
                    const size_t idx = ((size_t)(bb * H_ + hh) * L_ + l) * HD_ + d;
                    *(uint32_t*)((char*)OutH + idx * 2) = hi;
                } else {
                    float2 v = {v0, v1};
                    *(float2*)(OutF + (size_t)m * D_ + n0) = v;
                }
            }
        }
}

__global__ __launch_bounds__(512, 1)
void gemm_proj(const __half* __restrict__ Abase, const __half* __restrict__ WtBase,
               const float* __restrict__ bq, const float* __restrict__ bk,
               const float* __restrict__ bv, __half* __restrict__ QKV)
{
    const int z = blockIdx.z;
    const __half* A  = Abase  + (size_t)z * MROWS * KA_;
    const __half* Bt = WtBase + (size_t)z * D_ * KA_;
    const float* bias = (z == 0) ? bq : (z == 1) ? bk : bv;
    gemm_core<1>(A, Bt, bias, nullptr, QKV + (size_t)z * HSZ,
                 (z == 0) ? QSCALE : 1.0f);
}

__global__ __launch_bounds__(512, 1)
void gemm_out(const __half* __restrict__ A, const __half* __restrict__ Bt,
              const float* __restrict__ bias, float* __restrict__ Out)
{
    gemm_core<0>(A, Bt, bias, Out, nullptr, 1.0f);
}

// ============================================================================
// Flash attention fp16: CTA = 64 q-rows, 128 thr / 4 warps (warp = 16 rows).
// R8 softmax (fp32 ex2 + FADD row-sum + shfl, ballot-guarded rescale).
// 3-stage K/V cp.async ring -> ONE __syncthreads per tile:
//   iter t: issue t+2 into stage (t+2)%3 (== stage of tile t-1, whose readers
//   finished before the barrier that ended iter t-1), compute tile t,
//   then CPWAIT(1)+barrier to make tile t+1 resident and fence the next issue.
// SMEM: Q [0,0x2000); K stages [0x2000 + s*0x2000); V stages [0x8000 + s*0x2000).
// Total 56KB -> 4 CTAs/SM.
// ============================================================================
#define ATTN_SMEM 57344

__global__ __launch_bounds__(128, 4)
void attn_mma(const __half* __restrict__ Qg, const __half* __restrict__ Kg,
              const __half* __restrict__ Vg, __half* __restrict__ Aout)
{
    extern __shared__ __align__(128) char smem[];
    const uint32_t sb = smem_u32(smem);
    const int tid = threadIdx.x, lane = tid & 31, w = tid >> 5;
    const int q0 = blockIdx.x * 64;
    const int bh = blockIdx.y;
    const size_t base = (size_t)bh * L_ * HD_;

    const int lr = tid >> 3, lg = tid & 7;

    // Q tile -> [0, 0x2000)
#pragma unroll
    for (int j = 0; j < 4; j++) {
        const int r = 16 * j + lr;
        cp16(sb + r * 128 + ((lg ^ (r & 7)) << 4),
             Qg + base + (size_t)(q0 + r) * HD_ + lg * 8);
    }
    auto issueKV = [&](int t, int s) {
        const uint32_t kb = sb + 0x2000u + (uint32_t)s * 0x2000u;
        const uint32_t vb = sb + 0x8000u + (uint32_t)s * 0x2000u;
        const __half* ks = Kg + base + (size_t)(t * 64) * HD_;
        const __half* vs = Vg + base + (size_t)(t * 64) * HD_;
#pragma unroll
        for (int j = 0; j < 4; j++) {
            const int r = 16 * j + lr;
            const uint32_t off = r * 128 + ((lg ^ (r & 7)) << 4);
            cp16(kb + off, ks + (size_t)r * HD_ + lg * 8);
            cp16(vb + off, vs + (size_t)r * HD_ + lg * 8);
        }
    };
    issueKV(0, 0); CPCOMMIT();   // group0 = Q + KV tile 0
    issueKV(1, 1); CPCOMMIT();   // group1 = KV tile 1
    CPWAIT(1);                   // group0 done (Q + tile 0)
    __syncthreads();

    // separable swizzle pieces (all row indices = lane mod 8)
    uint32_t col[4];
#pragma unroll
    for (int i = 0; i < 4; i++)
        col[i] = sb + ((uint32_t)((2 * i + (lane >> 4)) ^ (lane & 7)) << 4);

    // hoisted Q fragments
    uint32_t qf[4][4];
#pragma unroll
    for (int kk = 0; kk < 4; kk++) {
        const uint32_t qrow = (uint32_t)(16 * w + (lane & 15)) * 128;
        ldsm4(qf[kk], col[kk] + qrow);
    }

    // consumer row offsets for stage 0 (sb NOT included; col[] carries sb)
    uint32_t krow[4], vrow[4];
#pragma unroll
    for (int i = 0; i < 4; i++) {
        krow[i] = 0x2000u + (uint32_t)(16 * i + (lane & 15)) * 128;
        vrow[i] = 0x8000u + (uint32_t)(16 * i + ((lane >> 3) & 1) * 8 + (lane & 7)) * 128;
    }

    float o[8][4];
#pragma unroll
    for (int j = 0; j < 8; j++)
#pragma unroll
        for (int k = 0; k < 4; k++) o[j][k] = 0.f;
    float mrow[2] = {-1e30f, -1e30f};
    float lrow[2] = {0.f, 0.f};

    int scur = 0;   // consumer stage
    int sn   = 2;   // producer stage for tile t+2

    for (int t = 0; t < 32; t++) {
        // issue tile t+2 (stage freed by tile t-1; fenced by last barrier)
        if (t + 2 < 32) issueKV(t + 2, sn);
        CPCOMMIT();
        sn = (sn == 2) ? 0 : sn + 1;

        // ---- S = Q.K^T (log2 domain) ----
        float sc[8][4];
#pragma unroll
        for (int j = 0; j < 8; j++)
#pragma unroll
            for (int k = 0; k < 4; k++) sc[j][k] = 0.f;

#pragma unroll
        for (int kk = 0; kk < 4; kk++) {
#pragma unroll
            for (int ntp = 0; ntp < 4; ntp++) {
                uint32_t khf[4];
                ldsm4(khf, krow[ntp] + col[kk]);
                mma16816(sc[2*ntp],   qf[kk], khf[0], khf[2]);
                mma16816(sc[2*ntp+1], qf[kk], khf[1], khf[3]);
            }
        }

        // ---- online softmax (fp32 ex2, both h-chains, one ballot) ----
        {
            float tm0 = -1e30f, tm1 = -1e30f;
#pragma unroll
            for (int nt = 0; nt < 8; nt++) {
                tm0 = fmaxf(tm0, fmaxf(sc[nt][0], sc[nt][1]));
                tm1 = fmaxf(tm1, fmaxf(sc[nt][2], sc[nt][3]));
            }
            tm0 = fmaxf(tm0, __shfl_xor_sync(0xffffffffu, tm0, 1));
            tm1 = fmaxf(tm1, __shfl_xor_sync(0xffffffffu, tm1, 1));
            tm0 = fmaxf(tm0, __shfl_xor_sync(0xffffffffu, tm0, 2));
            tm1 = fmaxf(tm1, __shfl_xor_sync(0xffffffffu, tm1, 2));
            const float mo0 = mrow[0], mo1 = mrow[1];
            const float mn0 = fmaxf(mo0, tm0), mn1 = fmaxf(mo1, tm1);
            mrow[0] = mn0; mrow[1] = mn1;
            float rs0 = 0.f, rs1 = 0.f;
#pragma unroll
            for (int nt = 0; nt < 8; nt++) {
                const float p0 = ex2(sc[nt][0] - mn0);
                const float p1 = ex2(sc[nt][1] - mn0);
                const float p2 = ex2(sc[nt][2] - mn1);
                const float p3 = ex2(sc[nt][3] - mn1);
                sc[nt][0] = p0; sc[nt][1] = p1; sc[nt][2] = p2; sc[nt][3] = p3;
                rs0 += p0 + p1;
                rs1 += p2 + p3;
            }
            rs0 += __shfl_xor_sync(0xffffffffu, rs0, 1);
            rs1 += __shfl_xor_sync(0xffffffffu, rs1, 1);
            rs0 += __shfl_xor_sync(0xffffffffu, rs0, 2);
            rs1 += __shfl_xor_sync(0xffffffffu, rs1, 2);
            if (__ballot_sync(0xffffffffu, (mn0 != mo0) || (mn1 != mo1))) {
                const float c0 = ex2(mo0 - mn0);
                const float c1 = ex2(mo1 - mn1);
                lrow[0] = lrow[0] * c0 + rs0;
                lrow[1] = lrow[1] * c1 + rs1;
#pragma unroll
                for (int nt = 0; nt < 8; nt++) {
                    o[nt][0] *= c0; o[nt][1] *= c0;
                    o[nt][2] *= c1; o[nt][3] *= c1;
                }
            } else {
                lrow[0] += rs0;
                lrow[1] += rs1;
            }
        }

        // ---- O += P.V (P packed fp16 in registers) ----
#pragma unroll
        for (int kk = 0; kk < 4; kk++) {
            uint32_t pa[4];
            {
                const float* s0 = sc[2*kk];
                const float* s1 = sc[2*kk+1];
                pa[0] = pack_hf2(s0[1], s0[0]);
                pa[1] = pack_hf2(s0[3], s0[2]);
                pa[2] = pack_hf2(s1[1], s1[0]);
                pa[3] = pack_hf2(s1[3], s1[2]);
            }
#pragma unroll
            for (int ntp = 0; ntp < 4; ntp++) {
                uint32_t vhf[4];
                ldsm4t(vhf, vrow[kk] + col[ntp]);
                mma16816(o[2*ntp],   pa, vhf[0], vhf[1]);
                mma16816(o[2*ntp+1], pa, vhf[2], vhf[3]);
            }
        }

        // advance consumer stage (0 -> 1 -> 2 -> 0 ...)
        {
            const uint32_t d = (scur == 2) ? (uint32_t)(-(int)0x4000) : 0x2000u;
#pragma unroll
            for (int i = 0; i < 4; i++) {
                krow[i] += d;
                vrow[i] += d;
            }
            scur = (scur == 2) ? 0 : scur + 1;
        }

        if (t < 31) {
            CPWAIT(1);          // tile t+1 resident (this thread)
            __syncthreads();    // CTA-wide visibility + WAR fence for next issue
        }
    }

    // ---- epilogue: normalize, fp16, write straight into A buffer ----
    const int b = bh >> 4, head = bh & 15;
#pragma unroll
    for (int h = 0; h < 2; h++) {
        const float inv = 1.f / lrow[h];
        const int qr = q0 + 16 * w + 8 * h + (lane >> 2);
        const int m = b * L_ + qr;
        __half* rowp = Aout + (size_t)m * KA_ + head * HD_ + (lane & 3) * 2;
#pragma unroll
        for (int nt = 0; nt < 8; nt++) {
            const uint32_t hv = pack_hf2(o[nt][2*h+1] * inv, o[nt][2*h] * inv);
            *(uint32_t*)(rowp + 8 * nt) = hv;
        }
    }
}

// ============================================================================
// launch
// ============================================================================
extern "C" void kernel_launch(void* const* d_in, const int* in_sizes, int n_in,
                              void* d_out, int out_size)
{
    const float* query = (const float*)d_in[0];
    const float* key_  = (const float*)d_in[1];
    const float* value = (const float*)d_in[2];
    const float* Wq = (const float*)d_in[3];
    const float* bq = (const float*)d_in[4];
    const float* Wk = (const float*)d_in[5];
    const float* bk = (const float*)d_in[6];
    const float* Wv = (const float*)d_in[7];
    const float* bv = (const float*)d_in[8];
    const float* Wo = (const float*)d_in[9];
    const float* bo = (const float*)d_in[10];
    float* out = (float*)d_out;

    __half *Ab, *Wt, *QKV;
    cudaGetSymbolAddress((void**)&Ab,  g_A);
    cudaGetSymbolAddress((void**)&Wt,  g_Wt);
    cudaGetSymbolAddress((void**)&QKV, g_QKV);

    cudaFuncSetAttribute(gemm_proj, cudaFuncAttributeMaxDynamicSharedMemorySize, G_SMEM);
    cudaFuncSetAttribute(gemm_out,  cudaFuncAttributeMaxDynamicSharedMemorySize, G_SMEM);
    cudaFuncSetAttribute(attn_mma,  cudaFuncAttributeMaxDynamicSharedMemorySize, ATTN_SMEM);

    // 1. weight conversion (batched z=4)
    dim3 wg(32, 32, 4), wb(32, 8);
    split_weightT4<<<wg, wb>>>(Wq, Wk, Wv, Wo, Wt);

    // 2. input conversion (batched z=3)
    dim3 sg(MROWS * D_ / 1024, 3);
    split_rows3<<<sg, 256>>>(query, key_, value, Ab);

    // 3. q/k/v projections (batched z=3)
    dim3 gg(D_ / 128, MROWS / 256, 3);
    gemm_proj<<<gg, 512, G_SMEM>>>(Ab, Wt, bq, bk, bv, QKV);

    // 4. attention (writes fp16 A for the output GEMM directly)
    dim3 ag(L_ / 64, B_ * H_);    // (32, 32) = 1024 CTAs
    attn_mma<<<ag, 128, ATTN_SMEM>>>(QKV, QKV + (size_t)1 * HSZ,
                                     QKV + (size_t)2 * HSZ, Ab);

    // 5. output projection
    dim3 og(D_ / 128, MROWS / 256);
    gemm_out<<<og, 512, G_SMEM>>>(Ab, Wt + (size_t)3 * D_ * KA_, bo, out);
}